// round 14
// baseline (speedup 1.0000x reference)
#include <cuda_runtime.h>
#include <cuda_bf16.h>
#include <cstdint>

#define Nn 64
#define Bb 256
#define Cc 256
#define Hh 4
#define HDd 64
#define Tt 8
#define Mm 128
#define Rr (Nn*Bb)   // 16384 rows

// ---------------- scratch (no allocations allowed) ----------------
__device__ __nv_bfloat16 g_msh[(size_t)Rr*Cc];   // msgs hi  [B*N, 256]
__device__ __nv_bfloat16 g_msl[(size_t)Rr*Cc];   // msgs lo
__device__ __nv_bfloat16 g_wbh[(size_t)Rr*Cc];   // wbuf hi  [N*B, 256]
__device__ __nv_bfloat16 g_wbl[(size_t)Rr*Cc];   // wbuf lo
__device__ __nv_bfloat16 g_hh [(size_t)Rr*Mm];   // h hi     [N*B, 128]
__device__ __nv_bfloat16 g_hl [(size_t)Rr*Mm];   // h lo
__device__ __nv_bfloat16 g_owt_h[(size_t)Cc*Cc]; // out_w^T hi  [n][k]
__device__ __nv_bfloat16 g_owt_l[(size_t)Cc*Cc];
__device__ __nv_bfloat16 g_bvt_h[(size_t)Cc*Cc]; // bv_w^T hi
__device__ __nv_bfloat16 g_bvt_l[(size_t)Cc*Cc];
__device__ __nv_bfloat16 g_w2t_h[(size_t)Cc*Mm]; // (bq_w@bk_w^T)^T hi [e][m]
__device__ __nv_bfloat16 g_w2t_l[(size_t)Cc*Mm];
__device__ float g_bqk [(size_t)Rr*Cc];          // [N*B, C]
__device__ float g_s   [(size_t)Rr];
__device__ float g_b2  [Cc];                     // bq_b @ bk_w^T
__device__ float g_u   [Mm + 1];                 // bq_w @ bk_b; [128]=bq_b.bk_b

// ================= helpers =================
__device__ __forceinline__ void bsplit(float x, __nv_bfloat16& hi, __nv_bfloat16& lo) {
    hi = __float2bfloat16(x);
    lo = __float2bfloat16(x - __bfloat162float(hi));
}
__device__ __forceinline__ uint32_t smem_u32(const void* p) {
    uint32_t a;
    asm("{ .reg .u64 t; cvta.to.shared.u64 t, %1; cvt.u32.u64 %0, t; }" : "=r"(a) : "l"(p));
    return a;
}
__device__ __forceinline__ void cp16(uint32_t d, const void* s) {
    asm volatile("cp.async.ca.shared.global [%0], [%1], 16;" :: "r"(d), "l"(s));
}
__device__ __forceinline__ void ldsm4(uint32_t* r, uint32_t a) {
    asm volatile("ldmatrix.sync.aligned.m8n8.x4.shared.b16 {%0,%1,%2,%3}, [%4];"
                 : "=r"(r[0]), "=r"(r[1]), "=r"(r[2]), "=r"(r[3]) : "r"(a));
}
__device__ __forceinline__ void mma16816(float* d, const uint32_t* a, const uint32_t* b) {
    asm volatile("mma.sync.aligned.m16n8k16.row.col.f32.bf16.bf16.f32 "
                 "{%0,%1,%2,%3}, {%4,%5,%6,%7}, {%8,%9}, {%0,%1,%2,%3};"
                 : "+f"(d[0]), "+f"(d[1]), "+f"(d[2]), "+f"(d[3])
                 : "r"(a[0]), "r"(a[1]), "r"(a[2]), "r"(a[3]), "r"(b[0]), "r"(b[1]));
}

// warp-level 16x32 tile of a 64x64x64 split-bf16 matmul (pitch 72 bf16 arrays)
__device__ __forceinline__ void warp_mm64(const __nv_bfloat16* Ah_, const __nv_bfloat16* Al_,
                                          const __nv_bfloat16* Bh_, const __nv_bfloat16* Bl_,
                                          int wband, int whalf, int lane, float acc[4][4]) {
    const int lg = lane >> 3, lr = lane & 7;
    #pragma unroll
    for (int kk = 0; kk < 4; kk++) {
        uint32_t Af[2][4];
        int arow = wband*16 + (lg & 1)*8 + lr;
        int akc  = kk*16 + (lg >> 1)*8;
        ldsm4(Af[0], smem_u32(Ah_ + arow*72 + akc));
        ldsm4(Af[1], smem_u32(Al_ + arow*72 + akc));
        uint32_t Bf[2][4][2];
        #pragma unroll
        for (int s = 0; s < 2; s++) {
            const __nv_bfloat16* Bp = s ? Bl_ : Bh_;
            #pragma unroll
            for (int nt2 = 0; nt2 < 2; nt2++) {
                int brow = whalf*32 + nt2*16 + (lg >> 1)*8 + lr;
                int bkc  = kk*16 + (lg & 1)*8;
                uint32_t r[4];
                ldsm4(r, smem_u32(Bp + brow*72 + bkc));
                Bf[s][nt2*2][0]   = r[0]; Bf[s][nt2*2][1]   = r[1];
                Bf[s][nt2*2+1][0] = r[2]; Bf[s][nt2*2+1][1] = r[3];
            }
        }
        #pragma unroll
        for (int nt = 0; nt < 4; nt++) {
            mma16816(acc[nt], Af[0], Bf[0][nt]);
            mma16816(acc[nt], Af[0], Bf[1][nt]);
            mma16816(acc[nt], Af[1], Bf[0][nt]);
        }
    }
}

// ============ weight folding ============
__global__ void fold_w2(const float* __restrict__ bq_w, const float* __restrict__ bk_w,
                        __nv_bfloat16* __restrict__ W2th, __nv_bfloat16* __restrict__ W2tl) {
    __shared__ float Aq[16*64];
    __shared__ float Bk[64*68];
    const int tid = threadIdx.x;
    const int m0 = blockIdx.x * 16;
    const int e0 = blockIdx.y * 64;
    const int e_l = tid & 63, grp = tid >> 6;
    float acc[4] = {0.f, 0.f, 0.f, 0.f};
    for (int c0 = 0; c0 < 256; c0 += 64) {
        {   int row = tid >> 4, col = (tid & 15) * 4;
            *(float4*)&Aq[row*64 + col] =
                *(const float4*)&bq_w[(size_t)(m0 + row) * 256 + c0 + col]; }
        #pragma unroll
        for (int i = 0; i < 4; i++) {
            int t = tid + i * 256;
            int row = t >> 4, col = (t & 15) * 4;
            *(float4*)&Bk[row*68 + col] =
                *(const float4*)&bk_w[(size_t)(e0 + row) * 256 + c0 + col];
        }
        __syncthreads();
        for (int c = 0; c < 64; c++) {
            float bv = Bk[e_l*68 + c];
            #pragma unroll
            for (int i = 0; i < 4; i++) acc[i] += Aq[(grp + 4*i)*64 + c] * bv;
        }
        __syncthreads();
    }
    #pragma unroll
    for (int i = 0; i < 4; i++) {
        __nv_bfloat16 hi, lo; bsplit(acc[i], hi, lo);
        size_t o = (size_t)(e0 + e_l) * Mm + (m0 + grp + 4*i);   // transposed [e][m]
        W2th[o] = hi; W2tl[o] = lo;
    }
}

// parallel: one block per output element (0..255 -> b2, 256..383 -> u, 384 -> u[128])
__global__ void fold_small(const float* __restrict__ bq_w, const float* __restrict__ bq_b,
                           const float* __restrict__ bk_w, const float* __restrict__ bk_b,
                           float* __restrict__ b2, float* __restrict__ u) {
    const int o = blockIdx.x;
    const int c = threadIdx.x;     // 256
    float val;
    if (o < 256)      val = bq_b[c] * bk_w[(size_t)o * 256 + c];
    else if (o < 384) val = bq_w[(size_t)(o - 256) * 256 + c] * bk_b[c];
    else              val = bq_b[c] * bk_b[c];
    #pragma unroll
    for (int off = 16; off > 0; off >>= 1) val += __shfl_xor_sync(0xffffffffu, val, off);
    __shared__ float red[8];
    if ((c & 31) == 0) red[c >> 5] = val;
    __syncthreads();
    if (c == 0) {
        float s = 0.f;
        #pragma unroll
        for (int w = 0; w < 8; w++) s += red[w];
        if (o < 256) b2[o] = s;
        else if (o < 384) u[o - 256] = s;
        else u[128] = s;
    }
}

// split h [N*B,128] into bf16 hi/lo — grid-stride float4
__global__ void split_h(const float* __restrict__ h, __nv_bfloat16* __restrict__ hh,
                        __nv_bfloat16* __restrict__ hl) {
    const long total4 = (long)Rr * Mm / 4;
    for (long i4 = (long)blockIdx.x * blockDim.x + threadIdx.x; i4 < total4;
         i4 += (long)gridDim.x * blockDim.x) {
        float4 x = ((const float4*)h)[i4];
        __nv_bfloat16 h0,l0,h1,l1,h2,l2,h3,l3;
        bsplit(x.x,h0,l0); bsplit(x.y,h1,l1); bsplit(x.z,h2,l2); bsplit(x.w,h3,l3);
        __nv_bfloat162 a{h0,h1}, b2{h2,h3}, c{l0,l1}, d2{l2,l3};
        *(__nv_bfloat162*)&hh[i4*4]     = a;
        *(__nv_bfloat162*)&hh[i4*4 + 2] = b2;
        *(__nv_bfloat162*)&hl[i4*4]     = c;
        *(__nv_bfloat162*)&hl[i4*4 + 2] = d2;
    }
}

// transpose + split a 256x256 weight: out[n][k] = bf16split(W[k][n])
__global__ void wsplit_t(const float* __restrict__ W, __nv_bfloat16* __restrict__ th,
                         __nv_bfloat16* __restrict__ tl) {
    __shared__ float tile[32][33];
    const int bx = blockIdx.x, by = blockIdx.y;
    const int tx = threadIdx.x & 31, ty0 = threadIdx.x >> 5;
    #pragma unroll
    for (int i = 0; i < 4; i++) {
        int kk = by*32 + ty0 + i*8;
        tile[ty0 + i*8][tx] = W[(size_t)kk * 256 + bx*32 + tx];
    }
    __syncthreads();
    #pragma unroll
    for (int i = 0; i < 4; i++) {
        int n = bx*32 + ty0 + i*8;
        int kk = by*32 + tx;
        __nv_bfloat16 hi, lo; bsplit(tile[tx][ty0 + i*8], hi, lo);
        th[(size_t)n*256 + kk] = hi; tl[(size_t)n*256 + kk] = lo;
    }
}

// ============ fused graph attention per (b,h) — hybrid: fp32 QK^T, HMMA A@V ============
__device__ __forceinline__ unsigned okey(float v) {
    unsigned u = __float_as_uint(v);
    return (u & 0x80000000u) ? ~u : (u | 0x80000000u);
}

#define ATTN_SMEM 54272

__global__ void attn_kernel(const float* __restrict__ q, const float* __restrict__ k,
                            const float* __restrict__ v, const float* __restrict__ sg,
                            const float* __restrict__ ctrl, const float* __restrict__ bond,
                            __nv_bfloat16* __restrict__ msh, __nv_bfloat16* __restrict__ msl,
                            float* __restrict__ attn_out) {
    extern __shared__ char smc[];
    float* QT = (float*)smc;                         // [64 d][68]
    float* KT = (float*)(smc + 17408);               // [64 d][68]
    __nv_bfloat16* Vh  = (__nv_bfloat16*)smc;        // [64 d][72]
    __nv_bfloat16* Vl  = (__nv_bfloat16*)(smc + 9216);
    __nv_bfloat16* Ash = (__nv_bfloat16*)(smc + 18432); // [64 n][72]
    __nv_bfloat16* Asl = (__nv_bfloat16*)(smc + 27648);
    float* Ls = (float*)(smc + 36864);               // [64 n][68]

    const int bid = blockIdx.x;
    const int b = bid >> 2;
    const int hh = bid & 3;
    const int tid = threadIdx.x, wid = tid >> 5, lane = tid & 31;

    // phase 1: load Q,K transposed fp32
    #pragma unroll
    for (int i = 0; i < 4; i++) {
        int t = tid + i * 256;
        int row = t >> 4;
        int col = (t & 15) * 4;
        size_t g = ((size_t)row * Bb + b) * Cc + hh * HDd + col;
        float4 qv = *(const float4*)&q[g];
        float4 kv = *(const float4*)&k[g];
        QT[(col+0)*68 + row] = qv.x; QT[(col+1)*68 + row] = qv.y;
        QT[(col+2)*68 + row] = qv.z; QT[(col+3)*68 + row] = qv.w;
        KT[(col+0)*68 + row] = kv.x; KT[(col+1)*68 + row] = kv.y;
        KT[(col+2)*68 + row] = kv.z; KT[(col+3)*68 + row] = kv.w;
    }
    __syncthreads();

    const int n0 = (tid >> 4) * 4;
    const int m0 = (tid & 15) * 4;

    // logits = Q @ K^T in fp32 (EXACT — selection depends on it)
    {
        float acc[4][4];
        #pragma unroll
        for (int i = 0; i < 4; i++)
            #pragma unroll
            for (int j = 0; j < 4; j++) acc[i][j] = 0.f;
        for (int d = 0; d < 64; d++) {
            float4 a  = *(float4*)&QT[d*68 + n0];
            float4 bv = *(float4*)&KT[d*68 + m0];
            float av[4] = {a.x, a.y, a.z, a.w};
            float bw[4] = {bv.x, bv.y, bv.z, bv.w};
            #pragma unroll
            for (int i = 0; i < 4; i++)
                #pragma unroll
                for (int j = 0; j < 4; j++) acc[i][j] += av[i] * bw[j];
        }
        float cb[4];
        #pragma unroll
        for (int j = 0; j < 4; j++)
            cb[j] = ctrl[((size_t)(m0 + j) * Bb + b) * Hh + hh];
        #pragma unroll
        for (int i = 0; i < 4; i++) {
            int n = n0 + i;
            float4 bd = *(const float4*)&bond[(size_t)n * Nn + m0];
            float vals[4];
            vals[0] = acc[i][0]*0.125f + bd.x + cb[0];
            vals[1] = acc[i][1]*0.125f + bd.y + cb[1];
            vals[2] = acc[i][2]*0.125f + bd.z + cb[2];
            vals[3] = acc[i][3]*0.125f + bd.w + cb[3];
            int dsel = n - m0;
            if (dsel >= 0 && dsel < 4) vals[dsel] = -1e30f;
            *(float4*)&Ls[n*68 + m0] = *(float4*)vals;
        }
    }
    __syncthreads();

    // phase 2a: load gated V as bf16 splits, VT layout [d][m]
    #pragma unroll
    for (int i = 0; i < 4; i++) {
        int t = tid + i * 256;
        int row = t >> 4;
        int col = (t & 15) * 4;
        size_t g = ((size_t)row * Bb + b) * Cc + hh * HDd + col;
        float4 vv = *(const float4*)&v[g];
        float4 gg = *(const float4*)&sg[g];
        vv.x *= gg.x; vv.y *= gg.y; vv.z *= gg.z; vv.w *= gg.w;
        float vs[4] = {vv.x, vv.y, vv.z, vv.w};
        #pragma unroll
        for (int j = 0; j < 4; j++) {
            __nv_bfloat16 hi, lo; bsplit(vs[j], hi, lo);
            Vh[(col + j)*72 + row] = hi;
            Vl[(col + j)*72 + row] = lo;
        }
    }

    // phase 2b: warp-parallel exact top-8 + softmax (two rows interleaved)
    const size_t ao_base = (((size_t)b * Hh + hh) * Nn) * Nn;
    for (int pp = 0; pp < 4; pp++) {
        const int rowA = wid * 8 + pp * 2;
        const int rowB = rowA + 1;
        float vA0 = Ls[rowA*68 + lane], vA1 = Ls[rowA*68 + lane + 32];
        float vB0 = Ls[rowB*68 + lane], vB1 = Ls[rowB*68 + lane + 32];
        unsigned kA0 = okey(vA0), kA1 = okey(vA1);
        unsigned kB0 = okey(vB0), kB1 = okey(vB1);
        bool sA0 = false, sA1 = false, sB0 = false, sB1 = false;
        float mxA = 0.f, mxB = 0.f;
        #pragma unroll
        for (int it = 0; it < 8; it++) {
            unsigned cA0 = sA0 ? 0u : kA0;
            unsigned cA1 = sA1 ? 0u : kA1;
            unsigned cB0 = sB0 ? 0u : kB0;
            unsigned cB1 = sB1 ? 0u : kB1;
            unsigned mA = cA0 > cA1 ? cA0 : cA1;
            unsigned mB = cB0 > cB1 ? cB0 : cB1;
            unsigned bestA = __reduce_max_sync(0xffffffffu, mA);
            unsigned bestB = __reduce_max_sync(0xffffffffu, mB);
            if (it == 0) {
                mxA = __uint_as_float((bestA & 0x80000000u) ? (bestA & 0x7fffffffu) : ~bestA);
                mxB = __uint_as_float((bestB & 0x80000000u) ? (bestB & 0x7fffffffu) : ~bestB);
            }
            unsigned bA0 = __ballot_sync(0xffffffffu, cA0 == bestA);
            unsigned bB0 = __ballot_sync(0xffffffffu, cB0 == bestB);
            if (bA0) {
                if (lane == __ffs(bA0) - 1) sA0 = true;
            } else {
                unsigned bA1 = __ballot_sync(0xffffffffu, cA1 == bestA);
                if (lane == __ffs(bA1) - 1) sA1 = true;
            }
            if (bB0) {
                if (lane == __ffs(bB0) - 1) sB0 = true;
            } else {
                unsigned bB1 = __ballot_sync(0xffffffffu, cB1 == bestB);
                if (lane == __ffs(bB1) - 1) sB1 = true;
            }
        }
        float eA0 = sA0 ? __expf(vA0 - mxA) : 0.f;
        float eA1 = sA1 ? __expf(vA1 - mxA) : 0.f;
        float eB0 = sB0 ? __expf(vB0 - mxB) : 0.f;
        float eB1 = sB1 ? __expf(vB1 - mxB) : 0.f;
        float sumA = eA0 + eA1, sumB = eB0 + eB1;
        #pragma unroll
        for (int o = 16; o > 0; o >>= 1) {
            sumA += __shfl_xor_sync(0xffffffffu, sumA, o);
            sumB += __shfl_xor_sync(0xffffffffu, sumB, o);
        }
        float invA = 1.f / sumA, invB = 1.f / sumB;
        eA0 *= invA; eA1 *= invA; eB0 *= invB; eB1 *= invB;
        attn_out[ao_base + (size_t)rowA * Nn + lane]      = eA0;
        attn_out[ao_base + (size_t)rowA * Nn + lane + 32] = eA1;
        attn_out[ao_base + (size_t)rowB * Nn + lane]      = eB0;
        attn_out[ao_base + (size_t)rowB * Nn + lane + 32] = eB1;
        __nv_bfloat16 hi, lo;
        bsplit(eA0, hi, lo); Ash[rowA*72 + lane] = hi;      Asl[rowA*72 + lane] = lo;
        bsplit(eA1, hi, lo); Ash[rowA*72 + lane + 32] = hi; Asl[rowA*72 + lane + 32] = lo;
        bsplit(eB0, hi, lo); Ash[rowB*72 + lane] = hi;      Asl[rowB*72 + lane] = lo;
        bsplit(eB1, hi, lo); Ash[rowB*72 + lane + 32] = hi; Asl[rowB*72 + lane + 32] = lo;
    }
    __syncthreads();

    // phase 2c: msgs = attn @ Vg via split-bf16 HMMA
    {
        const int wband = wid >> 1;
        const int whalf = wid & 1;
        const int g2 = lane >> 2, tg = lane & 3;
        float acc[4][4];
        #pragma unroll
        for (int nt = 0; nt < 4; nt++)
            #pragma unroll
            for (int j = 0; j < 4; j++) acc[nt][j] = 0.f;
        warp_mm64(Ash, Asl, Vh, Vl, wband, whalf, lane, acc);
        #pragma unroll
        for (int nt = 0; nt < 4; nt++)
            #pragma unroll
            for (int dd = 0; dd < 2; dd++) {
                int n = wband*16 + g2 + dd*8;
                int d0c = whalf*32 + nt*8 + tg*2;
                size_t o = ((size_t)b * Nn + n) * Cc + hh * HDd + d0c;
                __nv_bfloat16 h0,l0,h1,l1;
                bsplit(acc[nt][dd*2+0], h0, l0);
                bsplit(acc[nt][dd*2+1], h1, l1);
                __nv_bfloat162 ph{h0,h1}, pl{l0,l1};
                *(__nv_bfloat162*)&msh[o] = ph;
                *(__nv_bfloat162*)&msl[o] = pl;
            }
    }
}

// ============ split-bf16 HMMA GEMM: row-block = bx*rstride + rbase ============
struct EpiMsgs {
    const float* out_b; const float* recv; float* nb;
    __device__ __forceinline__ void store(int r, int c, float acc) const {
        int n = r & 63, b = r >> 6;
        size_t rb = (size_t)n * Bb + b;
        float val = (acc + out_b[c]) * recv[rb * Cc + c];
        nb[(rb * Tt + (Tt - 1)) * Cc + c] = val;
    }
};
struct EpiBias {
    float* out; const float* bias;
    __device__ __forceinline__ void store(int r, int c, float acc) const {
        out[(size_t)r * Cc + c] = acc + bias[c];
    }
};
struct EpiRead {
    float* out; const float* bias; const float* s;
    __device__ __forceinline__ void store(int r, int c, float acc) const {
        out[(size_t)r * Cc + c] = acc + s[r] * bias[c];
    }
};

#define GEMM_SMEM (40960 + 20480)

template<typename Epi>
__global__ void __launch_bounds__(256, 2)
gemm_mma(const __nv_bfloat16* __restrict__ Ah, const __nv_bfloat16* __restrict__ Al,
         const __nv_bfloat16* __restrict__ Bth, const __nv_bfloat16* __restrict__ Btl,
         int K, int rstride, int rbase, Epi epi) {
    extern __shared__ char smem[];
    const uint32_t sbA = smem_u32(smem);
    const uint32_t sbB = sbA + 40960;
    const int tid = threadIdx.x, wid = tid >> 5, lane = tid & 31;
    const int r0 = blockIdx.x * rstride + rbase, c0 = blockIdx.y * 64;
    const int wm = (wid & 3) * 32, wn = (wid >> 2) * 32;
    const int NS = K >> 5;

    float acc[2][4][4];
    #pragma unroll
    for (int mt = 0; mt < 2; mt++)
        #pragma unroll
        for (int nt = 0; nt < 4; nt++)
            #pragma unroll
            for (int j = 0; j < 4; j++) acc[mt][nt][j] = 0.f;

    auto loadChunk = [&](int stage, int buf) {
        const char* srcAh = (const char*)(Ah + (size_t)r0 * K + stage * 32);
        const char* srcAl = (const char*)(Al + (size_t)r0 * K + stage * 32);
        #pragma unroll
        for (int i = 0; i < 4; i++) {
            int ch = tid + i * 256;
            int s = ch >> 9;
            int rem = ch & 511;
            int row = rem >> 2, seg = rem & 3;
            uint32_t dst = sbA + (uint32_t)(((buf*2 + s)*128 + row) * 80 + seg * 16);
            const char* src = (s ? srcAl : srcAh) + (size_t)row * (K * 2) + seg * 16;
            cp16(dst, src);
        }
        const char* srcBh = (const char*)(Bth + (size_t)c0 * K + stage * 32);
        const char* srcBl = (const char*)(Btl + (size_t)c0 * K + stage * 32);
        #pragma unroll
        for (int i = 0; i < 2; i++) {
            int ch = tid + i * 256;
            int s = ch >> 8;
            int rem = ch & 255;
            int row = rem >> 2, seg = rem & 3;
            uint32_t dst = sbB + (uint32_t)(((buf*2 + s)*64 + row) * 80 + seg * 16);
            const char* src = (s ? srcBl : srcBh) + (size_t)row * (K * 2) + seg * 16;
            cp16(dst, src);
        }
        asm volatile("cp.async.commit_group;");
    };

    loadChunk(0, 0);

    const int lg = lane >> 3, lr = lane & 7;

    for (int i = 0; i < NS; i++) {
        if (i + 1 < NS) {
            loadChunk(i + 1, (i + 1) & 1);
            asm volatile("cp.async.wait_group 1;");
        } else {
            asm volatile("cp.async.wait_group 0;");
        }
        __syncthreads();
        int buf = i & 1;
        #pragma unroll
        for (int kk = 0; kk < 2; kk++) {
            uint32_t Af[2][2][4];
            uint32_t Bf[2][4][2];
            #pragma unroll
            for (int s = 0; s < 2; s++)
                #pragma unroll
                for (int mt = 0; mt < 2; mt++) {
                    int row = wm + mt*16 + (lg & 1)*8 + lr;
                    int kc  = kk*16 + (lg >> 1)*8;
                    ldsm4(Af[s][mt], sbA + (uint32_t)(((buf*2 + s)*128 + row)*80 + kc*2));
                }
            #pragma unroll
            for (int s = 0; s < 2; s++)
                #pragma unroll
                for (int nt2 = 0; nt2 < 2; nt2++) {
                    int row = wn + nt2*16 + (lg >> 1)*8 + lr;
                    int kc  = kk*16 + (lg & 1)*8;
                    uint32_t r[4];
                    ldsm4(r, sbB + (uint32_t)(((buf*2 + s)*64 + row)*80 + kc*2));
                    Bf[s][nt2*2][0]   = r[0]; Bf[s][nt2*2][1]   = r[1];
                    Bf[s][nt2*2+1][0] = r[2]; Bf[s][nt2*2+1][1] = r[3];
                }
            #pragma unroll
            for (int mt = 0; mt < 2; mt++)
                #pragma unroll
                for (int nt = 0; nt < 4; nt++) {
                    mma16816(acc[mt][nt], Af[0][mt], Bf[0][nt]);
                    mma16816(acc[mt][nt], Af[0][mt], Bf[1][nt]);
                    mma16816(acc[mt][nt], Af[1][mt], Bf[0][nt]);
                }
        }
        __syncthreads();
    }

    const int g = lane >> 2, tg = lane & 3;
    #pragma unroll
    for (int mt = 0; mt < 2; mt++)
        #pragma unroll
        for (int nt = 0; nt < 4; nt++) {
            int row = r0 + wm + mt*16 + g;
            int col = c0 + wn + nt*8 + tg*2;
            epi.store(row,     col,     acc[mt][nt][0]);
            epi.store(row,     col + 1, acc[mt][nt][1]);
            epi.store(row + 8, col,     acc[mt][nt][2]);
            epi.store(row + 8, col + 1, acc[mt][nt][3]);
        }
}

// ---------------- temporal: fused buffer-shift + ba softmax + weighted sum ----------------
// half launch: grid 8192 blocks, r = (bx>>7)*256 + b0 + (bx&127)
__global__ void temporal_kernel(const float* __restrict__ bqk,
                                const float* __restrict__ h,
                                const float* __restrict__ u,
                                const float* __restrict__ buffers,
                                float* __restrict__ newbuf,
                                const float* __restrict__ decay_logit,
                                __nv_bfloat16* __restrict__ wbh,
                                __nv_bfloat16* __restrict__ wbl,
                                float* __restrict__ svec, int b0) {
    const int r = ((blockIdx.x >> 7) << 8) + b0 + (blockIdx.x & 127);
    const int c = threadIdx.x;
    const float* ob = buffers + (size_t)r * (Tt * Cc);
    float* nb = newbuf + (size_t)r * (Tt * Cc);

    float qk = bqk[(size_t)r * Cc + c];
    float nbv[8];
    float p[9];
    #pragma unroll
    for (int t = 0; t < 7; t++) nbv[t] = ob[(t + 1) * Cc + c];
    nbv[7] = nb[7 * Cc + c];
    #pragma unroll
    for (int t = 0; t < 8; t++) p[t] = qk * nbv[t];
    p[8] = (c < Mm) ? h[(size_t)r * Mm + c] * u[c] : 0.f;

    // fused shift: write slots 0..6
    #pragma unroll
    for (int t = 0; t < 7; t++) nb[t * Cc + c] = nbv[t];

    #pragma unroll
    for (int t = 0; t < 9; t++)
        #pragma unroll
        for (int o = 16; o > 0; o >>= 1)
            p[t] += __shfl_xor_sync(0xffffffffu, p[t], o);

    __shared__ float red[8][9];
    __shared__ float wsh[8];
    __shared__ float ssh;
    int warp = c >> 5, lane = c & 31;
    if (lane == 0) {
        #pragma unroll
        for (int t = 0; t < 9; t++) red[warp][t] = p[t];
    }
    __syncthreads();
    if (c == 0) {
        float bqb = u[128];
        #pragma unroll
        for (int w = 0; w < 8; w++) bqb += red[w][8];
        float ba[8]; float mx = -3e38f;
        #pragma unroll
        for (int t = 0; t < 8; t++) {
            float s = 0.f;
            #pragma unroll
            for (int w = 0; w < 8; w++) s += red[w][t];
            ba[t] = (s + bqb) * 0.0625f;
            mx = fmaxf(mx, ba[t]);
        }
        float sum = 0.f;
        #pragma unroll
        for (int t = 0; t < 8; t++) { ba[t] = __expf(ba[t] - mx); sum += ba[t]; }
        float inv = 1.f / sum;
        float dec = 1.f / (1.f + __expf(-decay_logit[0]));
        float powv = dec, s2 = 0.f;
        float wv[8];
        for (int t = 7; t >= 0; t--) {
            wv[t] = ba[t] * inv * powv;
            powv *= dec;
            s2 += wv[t];
        }
        #pragma unroll
        for (int t = 0; t < 8; t++) wsh[t] = wv[t];
        ssh = s2;
    }
    __syncthreads();
    float acc = 0.f;
    #pragma unroll
    for (int t = 0; t < 8; t++) acc += wsh[t] * nbv[t];
    __nv_bfloat16 hi, lo; bsplit(acc, hi, lo);
    wbh[(size_t)r * Cc + c] = hi;
    wbl[(size_t)r * Cc + c] = lo;
    if (c == 0) svec[r] = ssh;
}

// ---------------- launch ----------------
struct LaunchCtx {
    cudaStream_t s1, s2;
    cudaEvent_t eF, e1, e2, eM0, eM1, eT0, eT1;
    LaunchCtx() {
        int lo, hi;
        cudaDeviceGetStreamPriorityRange(&lo, &hi);
        cudaStreamCreateWithPriority(&s1, cudaStreamNonBlocking, hi);
        cudaStreamCreateWithPriority(&s2, cudaStreamNonBlocking, hi);
        cudaEventCreateWithFlags(&eF,  cudaEventDisableTiming);
        cudaEventCreateWithFlags(&e1,  cudaEventDisableTiming);
        cudaEventCreateWithFlags(&e2,  cudaEventDisableTiming);
        cudaEventCreateWithFlags(&eM0, cudaEventDisableTiming);
        cudaEventCreateWithFlags(&eM1, cudaEventDisableTiming);
        cudaEventCreateWithFlags(&eT0, cudaEventDisableTiming);
        cudaEventCreateWithFlags(&eT1, cudaEventDisableTiming);
    }
};

extern "C" void kernel_launch(void* const* d_in, const int* in_sizes, int n_in,
                              void* d_out, int out_size) {
    (void)in_sizes; (void)n_in; (void)out_size;
    const float* q      = (const float*)d_in[0];
    const float* k      = (const float*)d_in[1];
    const float* v      = (const float*)d_in[2];
    const float* send   = (const float*)d_in[3];
    const float* recv   = (const float*)d_in[4];
    const float* ctrl   = (const float*)d_in[5];
    const float* h      = (const float*)d_in[6];
    const float* buffers= (const float*)d_in[7];
    const float* bond   = (const float*)d_in[8];
    const float* out_w  = (const float*)d_in[9];
    const float* out_b  = (const float*)d_in[10];
    const float* bq_w   = (const float*)d_in[11];
    const float* bq_b   = (const float*)d_in[12];
    const float* bk_w   = (const float*)d_in[13];
    const float* bk_b   = (const float*)d_in[14];
    const float* bv_w   = (const float*)d_in[15];
    const float* bv_b   = (const float*)d_in[16];
    const float* decay  = (const float*)d_in[17];

    float* out     = (float*)d_out;
    float* readout = out;                                   // [N,B,C]
    float* newbuf  = out + (size_t)Rr * Cc;                 // [N,B,T,C]
    float* attn    = newbuf + (size_t)Rr * Tt * Cc;         // [B,H,N,N]

    __nv_bfloat16 *p_msh, *p_msl, *p_wbh, *p_wbl, *p_hh, *p_hl;
    __nv_bfloat16 *p_owh, *p_owl, *p_bvh, *p_bvl, *p_w2h, *p_w2l;
    float *p_bqk, *p_s, *p_b2, *p_u;
    cudaGetSymbolAddress((void**)&p_msh, g_msh);
    cudaGetSymbolAddress((void**)&p_msl, g_msl);
    cudaGetSymbolAddress((void**)&p_wbh, g_wbh);
    cudaGetSymbolAddress((void**)&p_wbl, g_wbl);
    cudaGetSymbolAddress((void**)&p_hh,  g_hh);
    cudaGetSymbolAddress((void**)&p_hl,  g_hl);
    cudaGetSymbolAddress((void**)&p_owh, g_owt_h);
    cudaGetSymbolAddress((void**)&p_owl, g_owt_l);
    cudaGetSymbolAddress((void**)&p_bvh, g_bvt_h);
    cudaGetSymbolAddress((void**)&p_bvl, g_bvt_l);
    cudaGetSymbolAddress((void**)&p_w2h, g_w2t_h);
    cudaGetSymbolAddress((void**)&p_w2l, g_w2t_l);
    cudaGetSymbolAddress((void**)&p_bqk, g_bqk);
    cudaGetSymbolAddress((void**)&p_s,   g_s);
    cudaGetSymbolAddress((void**)&p_b2,  g_b2);
    cudaGetSymbolAddress((void**)&p_u,   g_u);

    cudaFuncSetAttribute(attn_kernel, cudaFuncAttributeMaxDynamicSharedMemorySize, ATTN_SMEM);
    cudaFuncSetAttribute(gemm_mma<EpiMsgs>, cudaFuncAttributeMaxDynamicSharedMemorySize, GEMM_SMEM);
    cudaFuncSetAttribute(gemm_mma<EpiBias>, cudaFuncAttributeMaxDynamicSharedMemorySize, GEMM_SMEM);
    cudaFuncSetAttribute(gemm_mma<EpiRead>, cudaFuncAttributeMaxDynamicSharedMemorySize, GEMM_SMEM);

    static LaunchCtx ctx;

    cudaEventRecord(ctx.eF, 0);
    cudaStreamWaitEvent(ctx.s1, ctx.eF, 0);
    cudaStreamWaitEvent(ctx.s2, ctx.eF, 0);

    // side streams first (priority; hidden under attn)
    wsplit_t<<<dim3(8, 8), 256, 0, ctx.s1>>>(out_w, p_owh, p_owl);
    wsplit_t<<<dim3(8, 8), 256, 0, ctx.s1>>>(bv_w, p_bvh, p_bvl);
    cudaEventRecord(ctx.e1, ctx.s1);

    fold_small<<<385, 256, 0, ctx.s2>>>(bq_w, bq_b, bk_w, bk_b, p_b2, p_u);
    fold_w2<<<dim3(8, 4), 256, 0, ctx.s2>>>(bq_w, bk_w, p_w2h, p_w2l);
    split_h<<<256, 256, 0, ctx.s2>>>(h, p_hh, p_hl);
    {   EpiBias e{p_bqk, p_b2};
        gemm_mma<EpiBias><<<dim3(128, 4), 256, GEMM_SMEM, ctx.s2>>>(
            p_hh, p_hl, p_w2h, p_w2l, 128, 128, 0, e); }
    cudaEventRecord(ctx.e2, ctx.s2);

    // main: attention (whole)
    attn_kernel<<<Bb * Hh, 256, ATTN_SMEM>>>(q, k, v, send, ctrl, bond, p_msh, p_msl, attn);

    // main: gemmMsgs H0 (rows r<8192 == b<128)
    cudaStreamWaitEvent(0, ctx.e1, 0);
    {   EpiMsgs e{out_b, recv, newbuf};
        gemm_mma<EpiMsgs><<<dim3(64, 4), 256, GEMM_SMEM>>>(
            p_msh, p_msl, p_owh, p_owl, 256, 128, 0, e); }
    cudaEventRecord(ctx.eM0, 0);

    // main: gemmMsgs H1 (rows r>=8192 == b>=128)
    {   EpiMsgs e{out_b, recv, newbuf};
        gemm_mma<EpiMsgs><<<dim3(64, 4), 256, GEMM_SMEM>>>(
            p_msh, p_msl, p_owh, p_owl, 256, 128, 8192, e); }
    cudaEventRecord(ctx.eM1, 0);

    // s1: temporal H0 (b<128) — needs msgsH0 + bqk (e2); runs ∥ msgsH1
    cudaStreamWaitEvent(ctx.s1, ctx.eM0, 0);
    cudaStreamWaitEvent(ctx.s1, ctx.e2, 0);
    temporal_kernel<<<8192, 256, 0, ctx.s1>>>(p_bqk, h, p_u, buffers, newbuf, decay,
                                              p_wbh, p_wbl, p_s, 0);
    cudaEventRecord(ctx.eT0, ctx.s1);

    // s1: temporal H1 (b>=128) — needs msgsH1; runs ∥ readH0
    cudaStreamWaitEvent(ctx.s1, ctx.eM1, 0);
    temporal_kernel<<<8192, 256, 0, ctx.s1>>>(p_bqk, h, p_u, buffers, newbuf, decay,
                                              p_wbh, p_wbl, p_s, 128);
    cudaEventRecord(ctx.eT1, ctx.s1);

    // main: gemmRead H0 (row tiles r0 = bx*256, covers b<128) — needs tempH0
    cudaStreamWaitEvent(0, ctx.eT0, 0);
    {   EpiRead e{readout, bv_b, p_s};
        gemm_mma<EpiRead><<<dim3(64, 4), 256, GEMM_SMEM>>>(
            p_wbh, p_wbl, p_bvh, p_bvl, 256, 256, 0, e); }

    // main: gemmRead H1 (row tiles r0 = bx*256+128, covers b>=128) — needs tempH1
    cudaStreamWaitEvent(0, ctx.eT1, 0);
    {   EpiRead e{readout, bv_b, p_s};
        gemm_mma<EpiRead><<<dim3(64, 4), 256, GEMM_SMEM>>>(
            p_wbh, p_wbl, p_bvh, p_bvl, 256, 256, 128, e); }
}

// round 15
// speedup vs baseline: 1.0086x; 1.0086x over previous
#include <cuda_runtime.h>
#include <cuda_bf16.h>
#include <cstdint>

#define Nn 64
#define Bb 256
#define Cc 256
#define Hh 4
#define HDd 64
#define Tt 8
#define Mm 128
#define Rr (Nn*Bb)   // 16384 rows

// ---------------- scratch (no allocations allowed) ----------------
__device__ __nv_bfloat16 g_msh[(size_t)Rr*Cc];   // msgs hi  [B*N, 256]
__device__ __nv_bfloat16 g_msl[(size_t)Rr*Cc];   // msgs lo
__device__ __nv_bfloat16 g_wbh[(size_t)Rr*Cc];   // wbuf hi  [N*B, 256]
__device__ __nv_bfloat16 g_wbl[(size_t)Rr*Cc];   // wbuf lo
__device__ __nv_bfloat16 g_hh [(size_t)Rr*Mm];   // h hi     [N*B, 128]
__device__ __nv_bfloat16 g_hl [(size_t)Rr*Mm];   // h lo
__device__ __nv_bfloat16 g_owt_h[(size_t)Cc*Cc]; // out_w^T hi  [n][k]
__device__ __nv_bfloat16 g_owt_l[(size_t)Cc*Cc];
__device__ __nv_bfloat16 g_bvt_h[(size_t)Cc*Cc]; // bv_w^T hi
__device__ __nv_bfloat16 g_bvt_l[(size_t)Cc*Cc];
__device__ __nv_bfloat16 g_w2t_h[(size_t)Cc*Mm]; // (bq_w@bk_w^T)^T hi [e][m]
__device__ __nv_bfloat16 g_w2t_l[(size_t)Cc*Mm];
__device__ float g_bqk [(size_t)Rr*Cc];          // [N*B, C]
__device__ float g_s   [(size_t)Rr];
__device__ float g_b2  [Cc];                     // bq_b @ bk_w^T
__device__ float g_u   [Mm + 1];                 // bq_w @ bk_b; [128]=bq_b.bk_b

// ================= helpers =================
__device__ __forceinline__ void bsplit(float x, __nv_bfloat16& hi, __nv_bfloat16& lo) {
    hi = __float2bfloat16(x);
    lo = __float2bfloat16(x - __bfloat162float(hi));
}
__device__ __forceinline__ uint32_t smem_u32(const void* p) {
    uint32_t a;
    asm("{ .reg .u64 t; cvta.to.shared.u64 t, %1; cvt.u32.u64 %0, t; }" : "=r"(a) : "l"(p));
    return a;
}
__device__ __forceinline__ void cp16(uint32_t d, const void* s) {
    asm volatile("cp.async.ca.shared.global [%0], [%1], 16;" :: "r"(d), "l"(s));
}
__device__ __forceinline__ void ldsm4(uint32_t* r, uint32_t a) {
    asm volatile("ldmatrix.sync.aligned.m8n8.x4.shared.b16 {%0,%1,%2,%3}, [%4];"
                 : "=r"(r[0]), "=r"(r[1]), "=r"(r[2]), "=r"(r[3]) : "r"(a));
}
__device__ __forceinline__ void mma16816(float* d, const uint32_t* a, const uint32_t* b) {
    asm volatile("mma.sync.aligned.m16n8k16.row.col.f32.bf16.bf16.f32 "
                 "{%0,%1,%2,%3}, {%4,%5,%6,%7}, {%8,%9}, {%0,%1,%2,%3};"
                 : "+f"(d[0]), "+f"(d[1]), "+f"(d[2]), "+f"(d[3])
                 : "r"(a[0]), "r"(a[1]), "r"(a[2]), "r"(a[3]), "r"(b[0]), "r"(b[1]));
}

// warp-level 16x32 tile of a 64x64x64 split-bf16 matmul (pitch 72 bf16 arrays)
__device__ __forceinline__ void warp_mm64(const __nv_bfloat16* Ah_, const __nv_bfloat16* Al_,
                                          const __nv_bfloat16* Bh_, const __nv_bfloat16* Bl_,
                                          int wband, int whalf, int lane, float acc[4][4]) {
    const int lg = lane >> 3, lr = lane & 7;
    #pragma unroll
    for (int kk = 0; kk < 4; kk++) {
        uint32_t Af[2][4];
        int arow = wband*16 + (lg & 1)*8 + lr;
        int akc  = kk*16 + (lg >> 1)*8;
        ldsm4(Af[0], smem_u32(Ah_ + arow*72 + akc));
        ldsm4(Af[1], smem_u32(Al_ + arow*72 + akc));
        uint32_t Bf[2][4][2];
        #pragma unroll
        for (int s = 0; s < 2; s++) {
            const __nv_bfloat16* Bp = s ? Bl_ : Bh_;
            #pragma unroll
            for (int nt2 = 0; nt2 < 2; nt2++) {
                int brow = whalf*32 + nt2*16 + (lg >> 1)*8 + lr;
                int bkc  = kk*16 + (lg & 1)*8;
                uint32_t r[4];
                ldsm4(r, smem_u32(Bp + brow*72 + bkc));
                Bf[s][nt2*2][0]   = r[0]; Bf[s][nt2*2][1]   = r[1];
                Bf[s][nt2*2+1][0] = r[2]; Bf[s][nt2*2+1][1] = r[3];
            }
        }
        #pragma unroll
        for (int nt = 0; nt < 4; nt++) {
            mma16816(acc[nt], Af[0], Bf[0][nt]);
            mma16816(acc[nt], Af[0], Bf[1][nt]);
            mma16816(acc[nt], Af[1], Bf[0][nt]);
        }
    }
}

// ============ weight folding ============
// W2^T[e][m] = sum_c bq_w[m][c]*bk_w[e][c]; grid (8 m-tiles, 16 e-tiles), 16x16 per block
__global__ void fold_w2(const float* __restrict__ bq_w, const float* __restrict__ bk_w,
                        __nv_bfloat16* __restrict__ W2th, __nv_bfloat16* __restrict__ W2tl) {
    __shared__ float Aq[16*260];
    __shared__ float Bk[16*260];
    const int tid = threadIdx.x;
    const int m0 = blockIdx.x * 16;
    const int e0 = blockIdx.y * 16;
    // load tiles: 16 rows x 256 floats = 1024 float4, 256 threads x 4
    #pragma unroll
    for (int i = 0; i < 4; i++) {
        int t = tid + i * 256;
        int row = t >> 6, c4 = (t & 63) * 4;
        *(float4*)&Aq[row*260 + c4] = *(const float4*)&bq_w[(size_t)(m0 + row) * 256 + c4];
        *(float4*)&Bk[row*260 + c4] = *(const float4*)&bk_w[(size_t)(e0 + row) * 256 + c4];
    }
    __syncthreads();
    const int m = tid >> 4, e = tid & 15;
    float acc = 0.f;
    #pragma unroll 4
    for (int c4 = 0; c4 < 256; c4 += 4) {
        float4 a = *(float4*)&Aq[m*260 + c4];
        float4 b = *(float4*)&Bk[e*260 + c4];
        acc += a.x*b.x + a.y*b.y + a.z*b.z + a.w*b.w;
    }
    __nv_bfloat16 hi, lo; bsplit(acc, hi, lo);
    size_t o = (size_t)(e0 + e) * Mm + (m0 + m);
    W2th[o] = hi; W2tl[o] = lo;
}

// parallel: one block per output element (0..255 -> b2, 256..383 -> u, 384 -> u[128])
__global__ void fold_small(const float* __restrict__ bq_w, const float* __restrict__ bq_b,
                           const float* __restrict__ bk_w, const float* __restrict__ bk_b,
                           float* __restrict__ b2, float* __restrict__ u) {
    const int o = blockIdx.x;
    const int c = threadIdx.x;     // 256
    float val;
    if (o < 256)      val = bq_b[c] * bk_w[(size_t)o * 256 + c];
    else if (o < 384) val = bq_w[(size_t)(o - 256) * 256 + c] * bk_b[c];
    else              val = bq_b[c] * bk_b[c];
    #pragma unroll
    for (int off = 16; off > 0; off >>= 1) val += __shfl_xor_sync(0xffffffffu, val, off);
    __shared__ float red[8];
    if ((c & 31) == 0) red[c >> 5] = val;
    __syncthreads();
    if (c == 0) {
        float s = 0.f;
        #pragma unroll
        for (int w = 0; w < 8; w++) s += red[w];
        if (o < 256) b2[o] = s;
        else if (o < 384) u[o - 256] = s;
        else u[128] = s;
    }
}

// split h [N*B,128] into bf16 hi/lo — grid-stride float4
__global__ void split_h(const float* __restrict__ h, __nv_bfloat16* __restrict__ hh,
                        __nv_bfloat16* __restrict__ hl) {
    const long total4 = (long)Rr * Mm / 4;
    for (long i4 = (long)blockIdx.x * blockDim.x + threadIdx.x; i4 < total4;
         i4 += (long)gridDim.x * blockDim.x) {
        float4 x = ((const float4*)h)[i4];
        __nv_bfloat16 h0,l0,h1,l1,h2,l2,h3,l3;
        bsplit(x.x,h0,l0); bsplit(x.y,h1,l1); bsplit(x.z,h2,l2); bsplit(x.w,h3,l3);
        __nv_bfloat162 a{h0,h1}, b2{h2,h3}, c{l0,l1}, d2{l2,l3};
        *(__nv_bfloat162*)&hh[i4*4]     = a;
        *(__nv_bfloat162*)&hh[i4*4 + 2] = b2;
        *(__nv_bfloat162*)&hl[i4*4]     = c;
        *(__nv_bfloat162*)&hl[i4*4 + 2] = d2;
    }
}

// transpose + split two 256x256 weights (z selects): out[n][k] = bf16split(W[k][n])
__global__ void wsplit_t2(const float* __restrict__ W0, __nv_bfloat16* __restrict__ th0,
                          __nv_bfloat16* __restrict__ tl0,
                          const float* __restrict__ W1, __nv_bfloat16* __restrict__ th1,
                          __nv_bfloat16* __restrict__ tl1) {
    const float* W = blockIdx.z ? W1 : W0;
    __nv_bfloat16* th = blockIdx.z ? th1 : th0;
    __nv_bfloat16* tl = blockIdx.z ? tl1 : tl0;
    __shared__ float tile[32][33];
    const int bx = blockIdx.x, by = blockIdx.y;
    const int tx = threadIdx.x & 31, ty0 = threadIdx.x >> 5;
    #pragma unroll
    for (int i = 0; i < 4; i++) {
        int kk = by*32 + ty0 + i*8;
        tile[ty0 + i*8][tx] = W[(size_t)kk * 256 + bx*32 + tx];
    }
    __syncthreads();
    #pragma unroll
    for (int i = 0; i < 4; i++) {
        int n = bx*32 + ty0 + i*8;
        int kk = by*32 + tx;
        __nv_bfloat16 hi, lo; bsplit(tile[tx][ty0 + i*8], hi, lo);
        th[(size_t)n*256 + kk] = hi; tl[(size_t)n*256 + kk] = lo;
    }
}

// ============ fused graph attention per (b,h) — hybrid: fp32 QK^T, HMMA A@V ============
__device__ __forceinline__ unsigned okey(float v) {
    unsigned u = __float_as_uint(v);
    return (u & 0x80000000u) ? ~u : (u | 0x80000000u);
}

#define ATTN_SMEM 54272

__global__ void attn_kernel(const float* __restrict__ q, const float* __restrict__ k,
                            const float* __restrict__ v, const float* __restrict__ sg,
                            const float* __restrict__ ctrl, const float* __restrict__ bond,
                            __nv_bfloat16* __restrict__ msh, __nv_bfloat16* __restrict__ msl,
                            float* __restrict__ attn_out) {
    extern __shared__ char smc[];
    float* QT = (float*)smc;                         // [64 d][68]
    float* KT = (float*)(smc + 17408);               // [64 d][68]
    __nv_bfloat16* Vh  = (__nv_bfloat16*)smc;        // [64 d][72]
    __nv_bfloat16* Vl  = (__nv_bfloat16*)(smc + 9216);
    __nv_bfloat16* Ash = (__nv_bfloat16*)(smc + 18432); // [64 n][72]
    __nv_bfloat16* Asl = (__nv_bfloat16*)(smc + 27648);
    float* Ls = (float*)(smc + 36864);               // [64 n][68]

    const int bid = blockIdx.x;
    const int b = bid >> 2;
    const int hh = bid & 3;
    const int tid = threadIdx.x, wid = tid >> 5, lane = tid & 31;

    // phase 1: load Q,K transposed fp32
    #pragma unroll
    for (int i = 0; i < 4; i++) {
        int t = tid + i * 256;
        int row = t >> 4;
        int col = (t & 15) * 4;
        size_t g = ((size_t)row * Bb + b) * Cc + hh * HDd + col;
        float4 qv = *(const float4*)&q[g];
        float4 kv = *(const float4*)&k[g];
        QT[(col+0)*68 + row] = qv.x; QT[(col+1)*68 + row] = qv.y;
        QT[(col+2)*68 + row] = qv.z; QT[(col+3)*68 + row] = qv.w;
        KT[(col+0)*68 + row] = kv.x; KT[(col+1)*68 + row] = kv.y;
        KT[(col+2)*68 + row] = kv.z; KT[(col+3)*68 + row] = kv.w;
    }
    __syncthreads();

    const int n0 = (tid >> 4) * 4;
    const int m0 = (tid & 15) * 4;

    // logits = Q @ K^T in fp32 (EXACT — selection depends on it)
    {
        float acc[4][4];
        #pragma unroll
        for (int i = 0; i < 4; i++)
            #pragma unroll
            for (int j = 0; j < 4; j++) acc[i][j] = 0.f;
        for (int d = 0; d < 64; d++) {
            float4 a  = *(float4*)&QT[d*68 + n0];
            float4 bv = *(float4*)&KT[d*68 + m0];
            float av[4] = {a.x, a.y, a.z, a.w};
            float bw[4] = {bv.x, bv.y, bv.z, bv.w};
            #pragma unroll
            for (int i = 0; i < 4; i++)
                #pragma unroll
                for (int j = 0; j < 4; j++) acc[i][j] += av[i] * bw[j];
        }
        float cb[4];
        #pragma unroll
        for (int j = 0; j < 4; j++)
            cb[j] = ctrl[((size_t)(m0 + j) * Bb + b) * Hh + hh];
        #pragma unroll
        for (int i = 0; i < 4; i++) {
            int n = n0 + i;
            float4 bd = *(const float4*)&bond[(size_t)n * Nn + m0];
            float vals[4];
            vals[0] = acc[i][0]*0.125f + bd.x + cb[0];
            vals[1] = acc[i][1]*0.125f + bd.y + cb[1];
            vals[2] = acc[i][2]*0.125f + bd.z + cb[2];
            vals[3] = acc[i][3]*0.125f + bd.w + cb[3];
            int dsel = n - m0;
            if (dsel >= 0 && dsel < 4) vals[dsel] = -1e30f;
            *(float4*)&Ls[n*68 + m0] = *(float4*)vals;
        }
    }
    __syncthreads();

    // phase 2a: load gated V as bf16 splits, VT layout [d][m]
    #pragma unroll
    for (int i = 0; i < 4; i++) {
        int t = tid + i * 256;
        int row = t >> 4;
        int col = (t & 15) * 4;
        size_t g = ((size_t)row * Bb + b) * Cc + hh * HDd + col;
        float4 vv = *(const float4*)&v[g];
        float4 gg = *(const float4*)&sg[g];
        vv.x *= gg.x; vv.y *= gg.y; vv.z *= gg.z; vv.w *= gg.w;
        float vs[4] = {vv.x, vv.y, vv.z, vv.w};
        #pragma unroll
        for (int j = 0; j < 4; j++) {
            __nv_bfloat16 hi, lo; bsplit(vs[j], hi, lo);
            Vh[(col + j)*72 + row] = hi;
            Vl[(col + j)*72 + row] = lo;
        }
    }

    // phase 2b: warp-parallel exact top-8 + softmax (two rows interleaved)
    const size_t ao_base = (((size_t)b * Hh + hh) * Nn) * Nn;
    for (int pp = 0; pp < 4; pp++) {
        const int rowA = wid * 8 + pp * 2;
        const int rowB = rowA + 1;
        float vA0 = Ls[rowA*68 + lane], vA1 = Ls[rowA*68 + lane + 32];
        float vB0 = Ls[rowB*68 + lane], vB1 = Ls[rowB*68 + lane + 32];
        unsigned kA0 = okey(vA0), kA1 = okey(vA1);
        unsigned kB0 = okey(vB0), kB1 = okey(vB1);
        bool sA0 = false, sA1 = false, sB0 = false, sB1 = false;
        float mxA = 0.f, mxB = 0.f;
        #pragma unroll
        for (int it = 0; it < 8; it++) {
            unsigned cA0 = sA0 ? 0u : kA0;
            unsigned cA1 = sA1 ? 0u : kA1;
            unsigned cB0 = sB0 ? 0u : kB0;
            unsigned cB1 = sB1 ? 0u : kB1;
            unsigned mA = cA0 > cA1 ? cA0 : cA1;
            unsigned mB = cB0 > cB1 ? cB0 : cB1;
            unsigned bestA = __reduce_max_sync(0xffffffffu, mA);
            unsigned bestB = __reduce_max_sync(0xffffffffu, mB);
            if (it == 0) {
                mxA = __uint_as_float((bestA & 0x80000000u) ? (bestA & 0x7fffffffu) : ~bestA);
                mxB = __uint_as_float((bestB & 0x80000000u) ? (bestB & 0x7fffffffu) : ~bestB);
            }
            unsigned bA0 = __ballot_sync(0xffffffffu, cA0 == bestA);
            unsigned bB0 = __ballot_sync(0xffffffffu, cB0 == bestB);
            if (bA0) {
                if (lane == __ffs(bA0) - 1) sA0 = true;
            } else {
                unsigned bA1 = __ballot_sync(0xffffffffu, cA1 == bestA);
                if (lane == __ffs(bA1) - 1) sA1 = true;
            }
            if (bB0) {
                if (lane == __ffs(bB0) - 1) sB0 = true;
            } else {
                unsigned bB1 = __ballot_sync(0xffffffffu, cB1 == bestB);
                if (lane == __ffs(bB1) - 1) sB1 = true;
            }
        }
        float eA0 = sA0 ? __expf(vA0 - mxA) : 0.f;
        float eA1 = sA1 ? __expf(vA1 - mxA) : 0.f;
        float eB0 = sB0 ? __expf(vB0 - mxB) : 0.f;
        float eB1 = sB1 ? __expf(vB1 - mxB) : 0.f;
        float sumA = eA0 + eA1, sumB = eB0 + eB1;
        #pragma unroll
        for (int o = 16; o > 0; o >>= 1) {
            sumA += __shfl_xor_sync(0xffffffffu, sumA, o);
            sumB += __shfl_xor_sync(0xffffffffu, sumB, o);
        }
        float invA = 1.f / sumA, invB = 1.f / sumB;
        eA0 *= invA; eA1 *= invA; eB0 *= invB; eB1 *= invB;
        attn_out[ao_base + (size_t)rowA * Nn + lane]      = eA0;
        attn_out[ao_base + (size_t)rowA * Nn + lane + 32] = eA1;
        attn_out[ao_base + (size_t)rowB * Nn + lane]      = eB0;
        attn_out[ao_base + (size_t)rowB * Nn + lane + 32] = eB1;
        __nv_bfloat16 hi, lo;
        bsplit(eA0, hi, lo); Ash[rowA*72 + lane] = hi;      Asl[rowA*72 + lane] = lo;
        bsplit(eA1, hi, lo); Ash[rowA*72 + lane + 32] = hi; Asl[rowA*72 + lane + 32] = lo;
        bsplit(eB0, hi, lo); Ash[rowB*72 + lane] = hi;      Asl[rowB*72 + lane] = lo;
        bsplit(eB1, hi, lo); Ash[rowB*72 + lane + 32] = hi; Asl[rowB*72 + lane + 32] = lo;
    }
    __syncthreads();

    // phase 2c: msgs = attn @ Vg via split-bf16 HMMA
    {
        const int wband = wid >> 1;
        const int whalf = wid & 1;
        const int g2 = lane >> 2, tg = lane & 3;
        float acc[4][4];
        #pragma unroll
        for (int nt = 0; nt < 4; nt++)
            #pragma unroll
            for (int j = 0; j < 4; j++) acc[nt][j] = 0.f;
        warp_mm64(Ash, Asl, Vh, Vl, wband, whalf, lane, acc);
        #pragma unroll
        for (int nt = 0; nt < 4; nt++)
            #pragma unroll
            for (int dd = 0; dd < 2; dd++) {
                int n = wband*16 + g2 + dd*8;
                int d0c = whalf*32 + nt*8 + tg*2;
                size_t o = ((size_t)b * Nn + n) * Cc + hh * HDd + d0c;
                __nv_bfloat16 h0,l0,h1,l1;
                bsplit(acc[nt][dd*2+0], h0, l0);
                bsplit(acc[nt][dd*2+1], h1, l1);
                __nv_bfloat162 ph{h0,h1}, pl{l0,l1};
                *(__nv_bfloat162*)&msh[o] = ph;
                *(__nv_bfloat162*)&msl[o] = pl;
            }
    }
}

// ============ split-bf16 HMMA GEMM: [16384 x K] @ [K x 256] ============
struct EpiMsgs {
    const float* out_b; const float* recv; float* nb;
    __device__ __forceinline__ void store(int r, int c, float acc) const {
        int n = r & 63, b = r >> 6;
        size_t rb = (size_t)n * Bb + b;
        float val = (acc + out_b[c]) * recv[rb * Cc + c];
        nb[(rb * Tt + (Tt - 1)) * Cc + c] = val;
    }
};
struct EpiBias {
    float* out; const float* bias;
    __device__ __forceinline__ void store(int r, int c, float acc) const {
        out[(size_t)r * Cc + c] = acc + bias[c];
    }
};
struct EpiRead {
    float* out; const float* bias; const float* s;
    __device__ __forceinline__ void store(int r, int c, float acc) const {
        out[(size_t)r * Cc + c] = acc + s[r] * bias[c];
    }
};

#define GEMM_SMEM (40960 + 20480)

template<typename Epi>
__global__ void __launch_bounds__(256, 2)
gemm_mma(const __nv_bfloat16* __restrict__ Ah, const __nv_bfloat16* __restrict__ Al,
         const __nv_bfloat16* __restrict__ Bth, const __nv_bfloat16* __restrict__ Btl,
         int K, Epi epi) {
    extern __shared__ char smem[];
    const uint32_t sbA = smem_u32(smem);
    const uint32_t sbB = sbA + 40960;
    const int tid = threadIdx.x, wid = tid >> 5, lane = tid & 31;
    const int r0 = blockIdx.x * 128, c0 = blockIdx.y * 64;
    const int wm = (wid & 3) * 32, wn = (wid >> 2) * 32;
    const int NS = K >> 5;

    float acc[2][4][4];
    #pragma unroll
    for (int mt = 0; mt < 2; mt++)
        #pragma unroll
        for (int nt = 0; nt < 4; nt++)
            #pragma unroll
            for (int j = 0; j < 4; j++) acc[mt][nt][j] = 0.f;

    auto loadChunk = [&](int stage, int buf) {
        const char* srcAh = (const char*)(Ah + (size_t)r0 * K + stage * 32);
        const char* srcAl = (const char*)(Al + (size_t)r0 * K + stage * 32);
        #pragma unroll
        for (int i = 0; i < 4; i++) {
            int ch = tid + i * 256;
            int s = ch >> 9;
            int rem = ch & 511;
            int row = rem >> 2, seg = rem & 3;
            uint32_t dst = sbA + (uint32_t)(((buf*2 + s)*128 + row) * 80 + seg * 16);
            const char* src = (s ? srcAl : srcAh) + (size_t)row * (K * 2) + seg * 16;
            cp16(dst, src);
        }
        const char* srcBh = (const char*)(Bth + (size_t)c0 * K + stage * 32);
        const char* srcBl = (const char*)(Btl + (size_t)c0 * K + stage * 32);
        #pragma unroll
        for (int i = 0; i < 2; i++) {
            int ch = tid + i * 256;
            int s = ch >> 8;
            int rem = ch & 255;
            int row = rem >> 2, seg = rem & 3;
            uint32_t dst = sbB + (uint32_t)(((buf*2 + s)*64 + row) * 80 + seg * 16);
            const char* src = (s ? srcBl : srcBh) + (size_t)row * (K * 2) + seg * 16;
            cp16(dst, src);
        }
        asm volatile("cp.async.commit_group;");
    };

    loadChunk(0, 0);

    const int lg = lane >> 3, lr = lane & 7;

    for (int i = 0; i < NS; i++) {
        if (i + 1 < NS) {
            loadChunk(i + 1, (i + 1) & 1);
            asm volatile("cp.async.wait_group 1;");
        } else {
            asm volatile("cp.async.wait_group 0;");
        }
        __syncthreads();
        int buf = i & 1;
        #pragma unroll
        for (int kk = 0; kk < 2; kk++) {
            uint32_t Af[2][2][4];
            uint32_t Bf[2][4][2];
            #pragma unroll
            for (int s = 0; s < 2; s++)
                #pragma unroll
                for (int mt = 0; mt < 2; mt++) {
                    int row = wm + mt*16 + (lg & 1)*8 + lr;
                    int kc  = kk*16 + (lg >> 1)*8;
                    ldsm4(Af[s][mt], sbA + (uint32_t)(((buf*2 + s)*128 + row)*80 + kc*2));
                }
            #pragma unroll
            for (int s = 0; s < 2; s++)
                #pragma unroll
                for (int nt2 = 0; nt2 < 2; nt2++) {
                    int row = wn + nt2*16 + (lg >> 1)*8 + lr;
                    int kc  = kk*16 + (lg & 1)*8;
                    uint32_t r[4];
                    ldsm4(r, sbB + (uint32_t)(((buf*2 + s)*64 + row)*80 + kc*2));
                    Bf[s][nt2*2][0]   = r[0]; Bf[s][nt2*2][1]   = r[1];
                    Bf[s][nt2*2+1][0] = r[2]; Bf[s][nt2*2+1][1] = r[3];
                }
            #pragma unroll
            for (int mt = 0; mt < 2; mt++)
                #pragma unroll
                for (int nt = 0; nt < 4; nt++) {
                    mma16816(acc[mt][nt], Af[0][mt], Bf[0][nt]);
                    mma16816(acc[mt][nt], Af[0][mt], Bf[1][nt]);
                    mma16816(acc[mt][nt], Af[1][mt], Bf[0][nt]);
                }
        }
        __syncthreads();
    }

    const int g = lane >> 2, tg = lane & 3;
    #pragma unroll
    for (int mt = 0; mt < 2; mt++)
        #pragma unroll
        for (int nt = 0; nt < 4; nt++) {
            int row = r0 + wm + mt*16 + g;
            int col = c0 + wn + nt*8 + tg*2;
            epi.store(row,     col,     acc[mt][nt][0]);
            epi.store(row,     col + 1, acc[mt][nt][1]);
            epi.store(row + 8, col,     acc[mt][nt][2]);
            epi.store(row + 8, col + 1, acc[mt][nt][3]);
        }
}

// ---------------- temporal: fused buffer-shift + ba softmax + weighted sum ----------------
__global__ void temporal_kernel(const float* __restrict__ bqk,
                                const float* __restrict__ h,
                                const float* __restrict__ u,
                                const float* __restrict__ buffers,
                                float* __restrict__ newbuf,
                                const float* __restrict__ decay_logit,
                                __nv_bfloat16* __restrict__ wbh,
                                __nv_bfloat16* __restrict__ wbl,
                                float* __restrict__ svec) {
    const int r = blockIdx.x;            // r = n*B + b
    const int c = threadIdx.x;           // 0..255
    const float* ob = buffers + (size_t)r * (Tt * Cc);
    float* nb = newbuf + (size_t)r * (Tt * Cc);

    float qk = bqk[(size_t)r * Cc + c];
    float nbv[8];
    float p[9];
    #pragma unroll
    for (int t = 0; t < 7; t++) nbv[t] = ob[(t + 1) * Cc + c];
    nbv[7] = nb[7 * Cc + c];
    #pragma unroll
    for (int t = 0; t < 8; t++) p[t] = qk * nbv[t];
    p[8] = (c < Mm) ? h[(size_t)r * Mm + c] * u[c] : 0.f;

    // fused shift: write slots 0..6
    #pragma unroll
    for (int t = 0; t < 7; t++) nb[t * Cc + c] = nbv[t];

    #pragma unroll
    for (int t = 0; t < 9; t++)
        #pragma unroll
        for (int o = 16; o > 0; o >>= 1)
            p[t] += __shfl_xor_sync(0xffffffffu, p[t], o);

    __shared__ float red[8][9];
    __shared__ float wsh[8];
    __shared__ float ssh;
    int warp = c >> 5, lane = c & 31;
    if (lane == 0) {
        #pragma unroll
        for (int t = 0; t < 9; t++) red[warp][t] = p[t];
    }
    __syncthreads();
    if (c == 0) {
        float bqb = u[128];
        #pragma unroll
        for (int w = 0; w < 8; w++) bqb += red[w][8];
        float ba[8]; float mx = -3e38f;
        #pragma unroll
        for (int t = 0; t < 8; t++) {
            float s = 0.f;
            #pragma unroll
            for (int w = 0; w < 8; w++) s += red[w][t];
            ba[t] = (s + bqb) * 0.0625f;
            mx = fmaxf(mx, ba[t]);
        }
        float sum = 0.f;
        #pragma unroll
        for (int t = 0; t < 8; t++) { ba[t] = __expf(ba[t] - mx); sum += ba[t]; }
        float inv = 1.f / sum;
        float dec = 1.f / (1.f + __expf(-decay_logit[0]));
        float powv = dec, s2 = 0.f;
        float wv[8];
        for (int t = 7; t >= 0; t--) {
            wv[t] = ba[t] * inv * powv;
            powv *= dec;
            s2 += wv[t];
        }
        #pragma unroll
        for (int t = 0; t < 8; t++) wsh[t] = wv[t];
        ssh = s2;
    }
    __syncthreads();
    float acc = 0.f;
    #pragma unroll
    for (int t = 0; t < 8; t++) acc += wsh[t] * nbv[t];
    __nv_bfloat16 hi, lo; bsplit(acc, hi, lo);
    wbh[(size_t)r * Cc + c] = hi;
    wbl[(size_t)r * Cc + c] = lo;
    if (c == 0) svec[r] = ssh;
}

// ---------------- launch ----------------
struct LaunchCtx {
    cudaStream_t s1, s2;
    cudaEvent_t eF, e1, e2;
    LaunchCtx() {
        int lo, hi;
        cudaDeviceGetStreamPriorityRange(&lo, &hi);
        cudaStreamCreateWithPriority(&s1, cudaStreamNonBlocking, hi);
        cudaStreamCreateWithPriority(&s2, cudaStreamNonBlocking, hi);
        cudaEventCreateWithFlags(&eF, cudaEventDisableTiming);
        cudaEventCreateWithFlags(&e1, cudaEventDisableTiming);
        cudaEventCreateWithFlags(&e2, cudaEventDisableTiming);
    }
};

extern "C" void kernel_launch(void* const* d_in, const int* in_sizes, int n_in,
                              void* d_out, int out_size) {
    (void)in_sizes; (void)n_in; (void)out_size;
    const float* q      = (const float*)d_in[0];
    const float* k      = (const float*)d_in[1];
    const float* v      = (const float*)d_in[2];
    const float* send   = (const float*)d_in[3];
    const float* recv   = (const float*)d_in[4];
    const float* ctrl   = (const float*)d_in[5];
    const float* h      = (const float*)d_in[6];
    const float* buffers= (const float*)d_in[7];
    const float* bond   = (const float*)d_in[8];
    const float* out_w  = (const float*)d_in[9];
    const float* out_b  = (const float*)d_in[10];
    const float* bq_w   = (const float*)d_in[11];
    const float* bq_b   = (const float*)d_in[12];
    const float* bk_w   = (const float*)d_in[13];
    const float* bk_b   = (const float*)d_in[14];
    const float* bv_w   = (const float*)d_in[15];
    const float* bv_b   = (const float*)d_in[16];
    const float* decay  = (const float*)d_in[17];

    float* out     = (float*)d_out;
    float* readout = out;                                   // [N,B,C]
    float* newbuf  = out + (size_t)Rr * Cc;                 // [N,B,T,C]
    float* attn    = newbuf + (size_t)Rr * Tt * Cc;         // [B,H,N,N]

    __nv_bfloat16 *p_msh, *p_msl, *p_wbh, *p_wbl, *p_hh, *p_hl;
    __nv_bfloat16 *p_owh, *p_owl, *p_bvh, *p_bvl, *p_w2h, *p_w2l;
    float *p_bqk, *p_s, *p_b2, *p_u;
    cudaGetSymbolAddress((void**)&p_msh, g_msh);
    cudaGetSymbolAddress((void**)&p_msl, g_msl);
    cudaGetSymbolAddress((void**)&p_wbh, g_wbh);
    cudaGetSymbolAddress((void**)&p_wbl, g_wbl);
    cudaGetSymbolAddress((void**)&p_hh,  g_hh);
    cudaGetSymbolAddress((void**)&p_hl,  g_hl);
    cudaGetSymbolAddress((void**)&p_owh, g_owt_h);
    cudaGetSymbolAddress((void**)&p_owl, g_owt_l);
    cudaGetSymbolAddress((void**)&p_bvh, g_bvt_h);
    cudaGetSymbolAddress((void**)&p_bvl, g_bvt_l);
    cudaGetSymbolAddress((void**)&p_w2h, g_w2t_h);
    cudaGetSymbolAddress((void**)&p_w2l, g_w2t_l);
    cudaGetSymbolAddress((void**)&p_bqk, g_bqk);
    cudaGetSymbolAddress((void**)&p_s,   g_s);
    cudaGetSymbolAddress((void**)&p_b2,  g_b2);
    cudaGetSymbolAddress((void**)&p_u,   g_u);

    cudaFuncSetAttribute(attn_kernel, cudaFuncAttributeMaxDynamicSharedMemorySize, ATTN_SMEM);
    cudaFuncSetAttribute(gemm_mma<EpiMsgs>, cudaFuncAttributeMaxDynamicSharedMemorySize, GEMM_SMEM);
    cudaFuncSetAttribute(gemm_mma<EpiBias>, cudaFuncAttributeMaxDynamicSharedMemorySize, GEMM_SMEM);
    cudaFuncSetAttribute(gemm_mma<EpiRead>, cudaFuncAttributeMaxDynamicSharedMemorySize, GEMM_SMEM);

    static LaunchCtx ctx;

    cudaEventRecord(ctx.eF, 0);
    cudaStreamWaitEvent(ctx.s1, ctx.eF, 0);
    cudaStreamWaitEvent(ctx.s2, ctx.eF, 0);

    // side streams first (priority; hidden under attn)
    // s1: both weight transposes in one launch
    wsplit_t2<<<dim3(8, 8, 2), 256, 0, ctx.s1>>>(out_w, p_owh, p_owl, bv_w, p_bvh, p_bvl);
    cudaEventRecord(ctx.e1, ctx.s1);

    // s2: bq/bk fold chain + bqk GEMM
    fold_small<<<385, 256, 0, ctx.s2>>>(bq_w, bq_b, bk_w, bk_b, p_b2, p_u);
    fold_w2<<<dim3(8, 16), 256, 0, ctx.s2>>>(bq_w, bk_w, p_w2h, p_w2l);
    split_h<<<1024, 256, 0, ctx.s2>>>(h, p_hh, p_hl);
    {   EpiBias e{p_bqk, p_b2};
        gemm_mma<EpiBias><<<dim3(128, 4), 256, GEMM_SMEM, ctx.s2>>>(p_hh, p_hl, p_w2h, p_w2l, 128, e); }
    cudaEventRecord(ctx.e2, ctx.s2);

    // main stream: attention (longest pole; backfills around side work)
    attn_kernel<<<Bb * Hh, 256, ATTN_SMEM>>>(q, k, v, send, ctrl, bond, p_msh, p_msl, attn);

    // join: msgs GEMM needs attn (main) + out_w split (s1)
    cudaStreamWaitEvent(0, ctx.e1, 0);
    {   EpiMsgs e{out_b, recv, newbuf};
        gemm_mma<EpiMsgs><<<dim3(128, 4), 256, GEMM_SMEM>>>(p_msh, p_msl, p_owh, p_owl, 256, e); }

    // temporal needs bqk (s2) + newbuf slot7 (main) + buffers
    cudaStreamWaitEvent(0, ctx.e2, 0);
    temporal_kernel<<<Rr, 256>>>(p_bqk, h, p_u, buffers, newbuf, decay, p_wbh, p_wbl, p_s);

    {   EpiRead e{readout, bv_b, p_s};
        gemm_mma<EpiRead><<<dim3(128, 4), 256, GEMM_SMEM>>>(p_wbh, p_wbl, p_bvh, p_bvl, 256, e); }
}

// round 16
// speedup vs baseline: 1.0528x; 1.0439x over previous
#include <cuda_runtime.h>
#include <cuda_bf16.h>
#include <cstdint>

#define Nn 64
#define Bb 256
#define Cc 256
#define Hh 4
#define HDd 64
#define Tt 8
#define Mm 128
#define Rr (Nn*Bb)   // 16384 rows

// ---------------- scratch (no allocations allowed) ----------------
__device__ __nv_bfloat16 g_msh[(size_t)Rr*Cc];   // msgs hi  [B*N, 256]
__device__ __nv_bfloat16 g_msl[(size_t)Rr*Cc];   // msgs lo
__device__ __nv_bfloat16 g_wbh[(size_t)Rr*Cc];   // wbuf hi  [N*B, 256]
__device__ __nv_bfloat16 g_wbl[(size_t)Rr*Cc];   // wbuf lo
__device__ __nv_bfloat16 g_hh [(size_t)Rr*Mm];   // h hi     [N*B, 128]
__device__ __nv_bfloat16 g_hl [(size_t)Rr*Mm];   // h lo
__device__ __nv_bfloat16 g_owt_h[(size_t)Cc*Cc]; // out_w^T hi  [n][k]
__device__ __nv_bfloat16 g_owt_l[(size_t)Cc*Cc];
__device__ __nv_bfloat16 g_bvt_h[(size_t)Cc*Cc]; // bv_w^T hi
__device__ __nv_bfloat16 g_bvt_l[(size_t)Cc*Cc];
__device__ __nv_bfloat16 g_w2t_h[(size_t)Cc*Mm]; // (bq_w@bk_w^T)^T hi [e][m]
__device__ __nv_bfloat16 g_w2t_l[(size_t)Cc*Mm];
__device__ float g_bqk [(size_t)Rr*Cc];          // [N*B, C]
__device__ float g_s   [(size_t)Rr];
__device__ float g_b2  [Cc];                     // bq_b @ bk_w^T
__device__ float g_u   [Mm + 1];                 // bq_w @ bk_b; [128]=bq_b.bk_b

// ================= helpers =================
__device__ __forceinline__ void bsplit(float x, __nv_bfloat16& hi, __nv_bfloat16& lo) {
    hi = __float2bfloat16(x);
    lo = __float2bfloat16(x - __bfloat162float(hi));
}
__device__ __forceinline__ uint32_t smem_u32(const void* p) {
    uint32_t a;
    asm("{ .reg .u64 t; cvta.to.shared.u64 t, %1; cvt.u32.u64 %0, t; }" : "=r"(a) : "l"(p));
    return a;
}
__device__ __forceinline__ void cp16(uint32_t d, const void* s) {
    asm volatile("cp.async.ca.shared.global [%0], [%1], 16;" :: "r"(d), "l"(s));
}
__device__ __forceinline__ void ldsm4(uint32_t* r, uint32_t a) {
    asm volatile("ldmatrix.sync.aligned.m8n8.x4.shared.b16 {%0,%1,%2,%3}, [%4];"
                 : "=r"(r[0]), "=r"(r[1]), "=r"(r[2]), "=r"(r[3]) : "r"(a));
}
__device__ __forceinline__ void mma16816(float* d, const uint32_t* a, const uint32_t* b) {
    asm volatile("mma.sync.aligned.m16n8k16.row.col.f32.bf16.bf16.f32 "
                 "{%0,%1,%2,%3}, {%4,%5,%6,%7}, {%8,%9}, {%0,%1,%2,%3};"
                 : "+f"(d[0]), "+f"(d[1]), "+f"(d[2]), "+f"(d[3])
                 : "r"(a[0]), "r"(a[1]), "r"(a[2]), "r"(a[3]), "r"(b[0]), "r"(b[1]));
}

// warp-level 16x32 tile of a 64x64x64 split-bf16 matmul (pitch 72 bf16 arrays)
__device__ __forceinline__ void warp_mm64(const __nv_bfloat16* Ah_, const __nv_bfloat16* Al_,
                                          const __nv_bfloat16* Bh_, const __nv_bfloat16* Bl_,
                                          int wband, int whalf, int lane, float acc[4][4]) {
    const int lg = lane >> 3, lr = lane & 7;
    #pragma unroll
    for (int kk = 0; kk < 4; kk++) {
        uint32_t Af[2][4];
        int arow = wband*16 + (lg & 1)*8 + lr;
        int akc  = kk*16 + (lg >> 1)*8;
        ldsm4(Af[0], smem_u32(Ah_ + arow*72 + akc));
        ldsm4(Af[1], smem_u32(Al_ + arow*72 + akc));
        uint32_t Bf[2][4][2];
        #pragma unroll
        for (int s = 0; s < 2; s++) {
            const __nv_bfloat16* Bp = s ? Bl_ : Bh_;
            #pragma unroll
            for (int nt2 = 0; nt2 < 2; nt2++) {
                int brow = whalf*32 + nt2*16 + (lg >> 1)*8 + lr;
                int bkc  = kk*16 + (lg & 1)*8;
                uint32_t r[4];
                ldsm4(r, smem_u32(Bp + brow*72 + bkc));
                Bf[s][nt2*2][0]   = r[0]; Bf[s][nt2*2][1]   = r[1];
                Bf[s][nt2*2+1][0] = r[2]; Bf[s][nt2*2+1][1] = r[3];
            }
        }
        #pragma unroll
        for (int nt = 0; nt < 4; nt++) {
            mma16816(acc[nt], Af[0], Bf[0][nt]);
            mma16816(acc[nt], Af[0], Bf[1][nt]);
            mma16816(acc[nt], Af[1], Bf[0][nt]);
        }
    }
}

// ============ weight folding ============
// W2^T[e][m] = sum_c bq_w[m][c]*bk_w[e][c]; grid (8 m-tiles, 16 e-tiles), 16x16 per block
__global__ void fold_w2(const float* __restrict__ bq_w, const float* __restrict__ bk_w,
                        __nv_bfloat16* __restrict__ W2th, __nv_bfloat16* __restrict__ W2tl) {
    __shared__ float Aq[16*260];
    __shared__ float Bk[16*260];
    const int tid = threadIdx.x;
    const int m0 = blockIdx.x * 16;
    const int e0 = blockIdx.y * 16;
    #pragma unroll
    for (int i = 0; i < 4; i++) {
        int t = tid + i * 256;
        int row = t >> 6, c4 = (t & 63) * 4;
        *(float4*)&Aq[row*260 + c4] = *(const float4*)&bq_w[(size_t)(m0 + row) * 256 + c4];
        *(float4*)&Bk[row*260 + c4] = *(const float4*)&bk_w[(size_t)(e0 + row) * 256 + c4];
    }
    __syncthreads();
    const int m = tid >> 4, e = tid & 15;
    float acc = 0.f;
    #pragma unroll 4
    for (int c4 = 0; c4 < 256; c4 += 4) {
        float4 a = *(float4*)&Aq[m*260 + c4];
        float4 b = *(float4*)&Bk[e*260 + c4];
        acc += a.x*b.x + a.y*b.y + a.z*b.z + a.w*b.w;
    }
    __nv_bfloat16 hi, lo; bsplit(acc, hi, lo);
    size_t o = (size_t)(e0 + e) * Mm + (m0 + m);
    W2th[o] = hi; W2tl[o] = lo;
}

// parallel: one block per output element (0..255 -> b2, 256..383 -> u, 384 -> u[128])
__global__ void fold_small(const float* __restrict__ bq_w, const float* __restrict__ bq_b,
                           const float* __restrict__ bk_w, const float* __restrict__ bk_b,
                           float* __restrict__ b2, float* __restrict__ u) {
    const int o = blockIdx.x;
    const int c = threadIdx.x;     // 256
    float val;
    if (o < 256)      val = bq_b[c] * bk_w[(size_t)o * 256 + c];
    else if (o < 384) val = bq_w[(size_t)(o - 256) * 256 + c] * bk_b[c];
    else              val = bq_b[c] * bk_b[c];
    #pragma unroll
    for (int off = 16; off > 0; off >>= 1) val += __shfl_xor_sync(0xffffffffu, val, off);
    __shared__ float red[8];
    if ((c & 31) == 0) red[c >> 5] = val;
    __syncthreads();
    if (c == 0) {
        float s = 0.f;
        #pragma unroll
        for (int w = 0; w < 8; w++) s += red[w];
        if (o < 256) b2[o] = s;
        else if (o < 384) u[o - 256] = s;
        else u[128] = s;
    }
}

// split h [N*B,128] into bf16 hi/lo — grid-stride float4
__global__ void split_h(const float* __restrict__ h, __nv_bfloat16* __restrict__ hh,
                        __nv_bfloat16* __restrict__ hl) {
    const long total4 = (long)Rr * Mm / 4;
    for (long i4 = (long)blockIdx.x * blockDim.x + threadIdx.x; i4 < total4;
         i4 += (long)gridDim.x * blockDim.x) {
        float4 x = ((const float4*)h)[i4];
        __nv_bfloat16 h0,l0,h1,l1,h2,l2,h3,l3;
        bsplit(x.x,h0,l0); bsplit(x.y,h1,l1); bsplit(x.z,h2,l2); bsplit(x.w,h3,l3);
        __nv_bfloat162 a{h0,h1}, b2{h2,h3}, c{l0,l1}, d2{l2,l3};
        *(__nv_bfloat162*)&hh[i4*4]     = a;
        *(__nv_bfloat162*)&hh[i4*4 + 2] = b2;
        *(__nv_bfloat162*)&hl[i4*4]     = c;
        *(__nv_bfloat162*)&hl[i4*4 + 2] = d2;
    }
}

// transpose + split two 256x256 weights (z selects): out[n][k] = bf16split(W[k][n])
__global__ void wsplit_t2(const float* __restrict__ W0, __nv_bfloat16* __restrict__ th0,
                          __nv_bfloat16* __restrict__ tl0,
                          const float* __restrict__ W1, __nv_bfloat16* __restrict__ th1,
                          __nv_bfloat16* __restrict__ tl1) {
    const float* W = blockIdx.z ? W1 : W0;
    __nv_bfloat16* th = blockIdx.z ? th1 : th0;
    __nv_bfloat16* tl = blockIdx.z ? tl1 : tl0;
    __shared__ float tile[32][33];
    const int bx = blockIdx.x, by = blockIdx.y;
    const int tx = threadIdx.x & 31, ty0 = threadIdx.x >> 5;
    #pragma unroll
    for (int i = 0; i < 4; i++) {
        int kk = by*32 + ty0 + i*8;
        tile[ty0 + i*8][tx] = W[(size_t)kk * 256 + bx*32 + tx];
    }
    __syncthreads();
    #pragma unroll
    for (int i = 0; i < 4; i++) {
        int n = bx*32 + ty0 + i*8;
        int kk = by*32 + tx;
        __nv_bfloat16 hi, lo; bsplit(tile[tx][ty0 + i*8], hi, lo);
        th[(size_t)n*256 + kk] = hi; tl[(size_t)n*256 + kk] = lo;
    }
}

// ============ fused graph attention per (b,h) — hybrid: fp32 QK^T, HMMA A@V ============
__device__ __forceinline__ unsigned okey(float v) {
    unsigned u = __float_as_uint(v);
    return (u & 0x80000000u) ? ~u : (u | 0x80000000u);
}

#define ATTN_SMEM 54272

__global__ void attn_kernel(const float* __restrict__ q, const float* __restrict__ k,
                            const float* __restrict__ v, const float* __restrict__ sg,
                            const float* __restrict__ ctrl, const float* __restrict__ bond,
                            __nv_bfloat16* __restrict__ msh, __nv_bfloat16* __restrict__ msl,
                            float* __restrict__ attn_out) {
    extern __shared__ char smc[];
    float* QT = (float*)smc;                         // [64 d][68]
    float* KT = (float*)(smc + 17408);               // [64 d][68]
    __nv_bfloat16* Vh  = (__nv_bfloat16*)smc;        // [64 d][72]
    __nv_bfloat16* Vl  = (__nv_bfloat16*)(smc + 9216);
    __nv_bfloat16* Ash = (__nv_bfloat16*)(smc + 18432); // [64 n][72]
    __nv_bfloat16* Asl = (__nv_bfloat16*)(smc + 27648);
    float* Ls = (float*)(smc + 36864);               // [64 n][68]

    const int bid = blockIdx.x;
    const int b = bid >> 2;
    const int hh = bid & 3;
    const int tid = threadIdx.x, wid = tid >> 5, lane = tid & 31;

    // phase 1: load Q,K transposed fp32
    #pragma unroll
    for (int i = 0; i < 4; i++) {
        int t = tid + i * 256;
        int row = t >> 4;
        int col = (t & 15) * 4;
        size_t g = ((size_t)row * Bb + b) * Cc + hh * HDd + col;
        float4 qv = *(const float4*)&q[g];
        float4 kv = *(const float4*)&k[g];
        QT[(col+0)*68 + row] = qv.x; QT[(col+1)*68 + row] = qv.y;
        QT[(col+2)*68 + row] = qv.z; QT[(col+3)*68 + row] = qv.w;
        KT[(col+0)*68 + row] = kv.x; KT[(col+1)*68 + row] = kv.y;
        KT[(col+2)*68 + row] = kv.z; KT[(col+3)*68 + row] = kv.w;
    }
    __syncthreads();

    const int n0 = (tid >> 4) * 4;
    const int m0 = (tid & 15) * 4;

    // logits = Q @ K^T in fp32 (EXACT — selection depends on it)
    {
        float acc[4][4];
        #pragma unroll
        for (int i = 0; i < 4; i++)
            #pragma unroll
            for (int j = 0; j < 4; j++) acc[i][j] = 0.f;
        for (int d = 0; d < 64; d++) {
            float4 a  = *(float4*)&QT[d*68 + n0];
            float4 bv = *(float4*)&KT[d*68 + m0];
            float av[4] = {a.x, a.y, a.z, a.w};
            float bw[4] = {bv.x, bv.y, bv.z, bv.w};
            #pragma unroll
            for (int i = 0; i < 4; i++)
                #pragma unroll
                for (int j = 0; j < 4; j++) acc[i][j] += av[i] * bw[j];
        }
        float cb[4];
        #pragma unroll
        for (int j = 0; j < 4; j++)
            cb[j] = ctrl[((size_t)(m0 + j) * Bb + b) * Hh + hh];
        #pragma unroll
        for (int i = 0; i < 4; i++) {
            int n = n0 + i;
            float4 bd = *(const float4*)&bond[(size_t)n * Nn + m0];
            float vals[4];
            vals[0] = acc[i][0]*0.125f + bd.x + cb[0];
            vals[1] = acc[i][1]*0.125f + bd.y + cb[1];
            vals[2] = acc[i][2]*0.125f + bd.z + cb[2];
            vals[3] = acc[i][3]*0.125f + bd.w + cb[3];
            int dsel = n - m0;
            if (dsel >= 0 && dsel < 4) vals[dsel] = -1e30f;
            *(float4*)&Ls[n*68 + m0] = *(float4*)vals;
        }
    }
    __syncthreads();

    // phase 2a: load gated V as bf16 splits, VT layout [d][m]
    #pragma unroll
    for (int i = 0; i < 4; i++) {
        int t = tid + i * 256;
        int row = t >> 4;
        int col = (t & 15) * 4;
        size_t g = ((size_t)row * Bb + b) * Cc + hh * HDd + col;
        float4 vv = *(const float4*)&v[g];
        float4 gg = *(const float4*)&sg[g];
        vv.x *= gg.x; vv.y *= gg.y; vv.z *= gg.z; vv.w *= gg.w;
        float vs[4] = {vv.x, vv.y, vv.z, vv.w};
        #pragma unroll
        for (int j = 0; j < 4; j++) {
            __nv_bfloat16 hi, lo; bsplit(vs[j], hi, lo);
            Vh[(col + j)*72 + row] = hi;
            Vl[(col + j)*72 + row] = lo;
        }
    }

    // phase 2b: warp-parallel exact top-8 + softmax (two rows interleaved)
    const size_t ao_base = (((size_t)b * Hh + hh) * Nn) * Nn;
    for (int pp = 0; pp < 4; pp++) {
        const int rowA = wid * 8 + pp * 2;
        const int rowB = rowA + 1;
        float vA0 = Ls[rowA*68 + lane], vA1 = Ls[rowA*68 + lane + 32];
        float vB0 = Ls[rowB*68 + lane], vB1 = Ls[rowB*68 + lane + 32];
        unsigned kA0 = okey(vA0), kA1 = okey(vA1);
        unsigned kB0 = okey(vB0), kB1 = okey(vB1);
        bool sA0 = false, sA1 = false, sB0 = false, sB1 = false;
        float mxA = 0.f, mxB = 0.f;
        #pragma unroll
        for (int it = 0; it < 8; it++) {
            unsigned cA0 = sA0 ? 0u : kA0;
            unsigned cA1 = sA1 ? 0u : kA1;
            unsigned cB0 = sB0 ? 0u : kB0;
            unsigned cB1 = sB1 ? 0u : kB1;
            unsigned mA = cA0 > cA1 ? cA0 : cA1;
            unsigned mB = cB0 > cB1 ? cB0 : cB1;
            unsigned bestA = __reduce_max_sync(0xffffffffu, mA);
            unsigned bestB = __reduce_max_sync(0xffffffffu, mB);
            if (it == 0) {
                mxA = __uint_as_float((bestA & 0x80000000u) ? (bestA & 0x7fffffffu) : ~bestA);
                mxB = __uint_as_float((bestB & 0x80000000u) ? (bestB & 0x7fffffffu) : ~bestB);
            }
            unsigned bA0 = __ballot_sync(0xffffffffu, cA0 == bestA);
            unsigned bB0 = __ballot_sync(0xffffffffu, cB0 == bestB);
            if (bA0) {
                if (lane == __ffs(bA0) - 1) sA0 = true;
            } else {
                unsigned bA1 = __ballot_sync(0xffffffffu, cA1 == bestA);
                if (lane == __ffs(bA1) - 1) sA1 = true;
            }
            if (bB0) {
                if (lane == __ffs(bB0) - 1) sB0 = true;
            } else {
                unsigned bB1 = __ballot_sync(0xffffffffu, cB1 == bestB);
                if (lane == __ffs(bB1) - 1) sB1 = true;
            }
        }
        float eA0 = sA0 ? __expf(vA0 - mxA) : 0.f;
        float eA1 = sA1 ? __expf(vA1 - mxA) : 0.f;
        float eB0 = sB0 ? __expf(vB0 - mxB) : 0.f;
        float eB1 = sB1 ? __expf(vB1 - mxB) : 0.f;
        float sumA = eA0 + eA1, sumB = eB0 + eB1;
        #pragma unroll
        for (int o = 16; o > 0; o >>= 1) {
            sumA += __shfl_xor_sync(0xffffffffu, sumA, o);
            sumB += __shfl_xor_sync(0xffffffffu, sumB, o);
        }
        float invA = 1.f / sumA, invB = 1.f / sumB;
        eA0 *= invA; eA1 *= invA; eB0 *= invB; eB1 *= invB;
        attn_out[ao_base + (size_t)rowA * Nn + lane]      = eA0;
        attn_out[ao_base + (size_t)rowA * Nn + lane + 32] = eA1;
        attn_out[ao_base + (size_t)rowB * Nn + lane]      = eB0;
        attn_out[ao_base + (size_t)rowB * Nn + lane + 32] = eB1;
        __nv_bfloat16 hi, lo;
        bsplit(eA0, hi, lo); Ash[rowA*72 + lane] = hi;      Asl[rowA*72 + lane] = lo;
        bsplit(eA1, hi, lo); Ash[rowA*72 + lane + 32] = hi; Asl[rowA*72 + lane + 32] = lo;
        bsplit(eB0, hi, lo); Ash[rowB*72 + lane] = hi;      Asl[rowB*72 + lane] = lo;
        bsplit(eB1, hi, lo); Ash[rowB*72 + lane + 32] = hi; Asl[rowB*72 + lane + 32] = lo;
    }
    __syncthreads();

    // phase 2c: msgs = attn @ Vg via split-bf16 HMMA
    {
        const int wband = wid >> 1;
        const int whalf = wid & 1;
        const int g2 = lane >> 2, tg = lane & 3;
        float acc[4][4];
        #pragma unroll
        for (int nt = 0; nt < 4; nt++)
            #pragma unroll
            for (int j = 0; j < 4; j++) acc[nt][j] = 0.f;
        warp_mm64(Ash, Asl, Vh, Vl, wband, whalf, lane, acc);
        #pragma unroll
        for (int nt = 0; nt < 4; nt++)
            #pragma unroll
            for (int dd = 0; dd < 2; dd++) {
                int n = wband*16 + g2 + dd*8;
                int d0c = whalf*32 + nt*8 + tg*2;
                size_t o = ((size_t)b * Nn + n) * Cc + hh * HDd + d0c;
                __nv_bfloat16 h0,l0,h1,l1;
                bsplit(acc[nt][dd*2+0], h0, l0);
                bsplit(acc[nt][dd*2+1], h1, l1);
                __nv_bfloat162 ph{h0,h1}, pl{l0,l1};
                *(__nv_bfloat162*)&msh[o] = ph;
                *(__nv_bfloat162*)&msl[o] = pl;
            }
    }
}

// ============ split-bf16 HMMA GEMM: [16384 x K] @ [K x 256] ============
// epilogues take contiguous column pairs (c, c+1) — float2 vectorized
struct EpiMsgs {
    const float* out_b; const float* recv; float* nb;
    __device__ __forceinline__ void store2(int r, int c, float a0, float a1) const {
        int n = r & 63, b = r >> 6;
        size_t rb = (size_t)n * Bb + b;
        float2 rv = *(const float2*)&recv[rb * Cc + c];
        float2 bb = *(const float2*)&out_b[c];
        float2 ov{(a0 + bb.x) * rv.x, (a1 + bb.y) * rv.y};
        *(float2*)&nb[(rb * Tt + (Tt - 1)) * Cc + c] = ov;
    }
};
struct EpiBias {
    float* out; const float* bias;
    __device__ __forceinline__ void store2(int r, int c, float a0, float a1) const {
        float2 bb = *(const float2*)&bias[c];
        float2 ov{a0 + bb.x, a1 + bb.y};
        *(float2*)&out[(size_t)r * Cc + c] = ov;
    }
};
struct EpiRead {
    float* out; const float* bias; const float* s;
    __device__ __forceinline__ void store2(int r, int c, float a0, float a1) const {
        float2 bb = *(const float2*)&bias[c];
        float sv = s[r];
        float2 ov{a0 + sv * bb.x, a1 + sv * bb.y};
        *(float2*)&out[(size_t)r * Cc + c] = ov;
    }
};

#define GEMM_SMEM (40960 + 20480)

template<typename Epi>
__global__ void __launch_bounds__(256, 2)
gemm_mma(const __nv_bfloat16* __restrict__ Ah, const __nv_bfloat16* __restrict__ Al,
         const __nv_bfloat16* __restrict__ Bth, const __nv_bfloat16* __restrict__ Btl,
         int K, Epi epi) {
    extern __shared__ char smem[];
    const uint32_t sbA = smem_u32(smem);
    const uint32_t sbB = sbA + 40960;
    const int tid = threadIdx.x, wid = tid >> 5, lane = tid & 31;
    const int r0 = blockIdx.x * 128, c0 = blockIdx.y * 64;
    const int wm = (wid & 3) * 32, wn = (wid >> 2) * 32;
    const int NS = K >> 5;

    float acc[2][4][4];
    #pragma unroll
    for (int mt = 0; mt < 2; mt++)
        #pragma unroll
        for (int nt = 0; nt < 4; nt++)
            #pragma unroll
            for (int j = 0; j < 4; j++) acc[mt][nt][j] = 0.f;

    auto loadChunk = [&](int stage, int buf) {
        const char* srcAh = (const char*)(Ah + (size_t)r0 * K + stage * 32);
        const char* srcAl = (const char*)(Al + (size_t)r0 * K + stage * 32);
        #pragma unroll
        for (int i = 0; i < 4; i++) {
            int ch = tid + i * 256;
            int s = ch >> 9;
            int rem = ch & 511;
            int row = rem >> 2, seg = rem & 3;
            uint32_t dst = sbA + (uint32_t)(((buf*2 + s)*128 + row) * 80 + seg * 16);
            const char* src = (s ? srcAl : srcAh) + (size_t)row * (K * 2) + seg * 16;
            cp16(dst, src);
        }
        const char* srcBh = (const char*)(Bth + (size_t)c0 * K + stage * 32);
        const char* srcBl = (const char*)(Btl + (size_t)c0 * K + stage * 32);
        #pragma unroll
        for (int i = 0; i < 2; i++) {
            int ch = tid + i * 256;
            int s = ch >> 8;
            int rem = ch & 255;
            int row = rem >> 2, seg = rem & 3;
            uint32_t dst = sbB + (uint32_t)(((buf*2 + s)*64 + row) * 80 + seg * 16);
            const char* src = (s ? srcBl : srcBh) + (size_t)row * (K * 2) + seg * 16;
            cp16(dst, src);
        }
        asm volatile("cp.async.commit_group;");
    };

    loadChunk(0, 0);

    const int lg = lane >> 3, lr = lane & 7;

    for (int i = 0; i < NS; i++) {
        if (i + 1 < NS) {
            loadChunk(i + 1, (i + 1) & 1);
            asm volatile("cp.async.wait_group 1;");
        } else {
            asm volatile("cp.async.wait_group 0;");
        }
        __syncthreads();
        int buf = i & 1;
        #pragma unroll
        for (int kk = 0; kk < 2; kk++) {
            uint32_t Af[2][2][4];
            uint32_t Bf[2][4][2];
            #pragma unroll
            for (int s = 0; s < 2; s++)
                #pragma unroll
                for (int mt = 0; mt < 2; mt++) {
                    int row = wm + mt*16 + (lg & 1)*8 + lr;
                    int kc  = kk*16 + (lg >> 1)*8;
                    ldsm4(Af[s][mt], sbA + (uint32_t)(((buf*2 + s)*128 + row)*80 + kc*2));
                }
            #pragma unroll
            for (int s = 0; s < 2; s++)
                #pragma unroll
                for (int nt2 = 0; nt2 < 2; nt2++) {
                    int row = wn + nt2*16 + (lg >> 1)*8 + lr;
                    int kc  = kk*16 + (lg & 1)*8;
                    uint32_t r[4];
                    ldsm4(r, sbB + (uint32_t)(((buf*2 + s)*64 + row)*80 + kc*2));
                    Bf[s][nt2*2][0]   = r[0]; Bf[s][nt2*2][1]   = r[1];
                    Bf[s][nt2*2+1][0] = r[2]; Bf[s][nt2*2+1][1] = r[3];
                }
            #pragma unroll
            for (int mt = 0; mt < 2; mt++)
                #pragma unroll
                for (int nt = 0; nt < 4; nt++) {
                    mma16816(acc[mt][nt], Af[0][mt], Bf[0][nt]);
                    mma16816(acc[mt][nt], Af[0][mt], Bf[1][nt]);
                    mma16816(acc[mt][nt], Af[1][mt], Bf[0][nt]);
                }
        }
        __syncthreads();
    }

    const int g = lane >> 2, tg = lane & 3;
    #pragma unroll
    for (int mt = 0; mt < 2; mt++)
        #pragma unroll
        for (int nt = 0; nt < 4; nt++) {
            int row = r0 + wm + mt*16 + g;
            int col = c0 + wn + nt*8 + tg*2;
            epi.store2(row,     col, acc[mt][nt][0], acc[mt][nt][1]);
            epi.store2(row + 8, col, acc[mt][nt][2], acc[mt][nt][3]);
        }
}

// ---------------- temporal: fused buffer-shift + ba softmax + weighted sum ----------------
__global__ void temporal_kernel(const float* __restrict__ bqk,
                                const float* __restrict__ h,
                                const float* __restrict__ u,
                                const float* __restrict__ buffers,
                                float* __restrict__ newbuf,
                                const float* __restrict__ decay_logit,
                                __nv_bfloat16* __restrict__ wbh,
                                __nv_bfloat16* __restrict__ wbl,
                                float* __restrict__ svec) {
    const int r = blockIdx.x;            // r = n*B + b
    const int c = threadIdx.x;           // 0..255
    const float* ob = buffers + (size_t)r * (Tt * Cc);
    float* nb = newbuf + (size_t)r * (Tt * Cc);

    float qk = bqk[(size_t)r * Cc + c];
    float nbv[8];
    float p[9];
    #pragma unroll
    for (int t = 0; t < 7; t++) nbv[t] = ob[(t + 1) * Cc + c];
    nbv[7] = nb[7 * Cc + c];
    #pragma unroll
    for (int t = 0; t < 8; t++) p[t] = qk * nbv[t];
    p[8] = (c < Mm) ? h[(size_t)r * Mm + c] * u[c] : 0.f;

    // fused shift: write slots 0..6
    #pragma unroll
    for (int t = 0; t < 7; t++) nb[t * Cc + c] = nbv[t];

    #pragma unroll
    for (int t = 0; t < 9; t++)
        #pragma unroll
        for (int o = 16; o > 0; o >>= 1)
            p[t] += __shfl_xor_sync(0xffffffffu, p[t], o);

    __shared__ float red[8][9];
    __shared__ float wsh[8];
    __shared__ float ssh;
    int warp = c >> 5, lane = c & 31;
    if (lane == 0) {
        #pragma unroll
        for (int t = 0; t < 9; t++) red[warp][t] = p[t];
    }
    __syncthreads();
    if (c == 0) {
        float bqb = u[128];
        #pragma unroll
        for (int w = 0; w < 8; w++) bqb += red[w][8];
        float ba[8]; float mx = -3e38f;
        #pragma unroll
        for (int t = 0; t < 8; t++) {
            float s = 0.f;
            #pragma unroll
            for (int w = 0; w < 8; w++) s += red[w][t];
            ba[t] = (s + bqb) * 0.0625f;
            mx = fmaxf(mx, ba[t]);
        }
        float sum = 0.f;
        #pragma unroll
        for (int t = 0; t < 8; t++) { ba[t] = __expf(ba[t] - mx); sum += ba[t]; }
        float inv = 1.f / sum;
        float dec = 1.f / (1.f + __expf(-decay_logit[0]));
        float powv = dec, s2 = 0.f;
        float wv[8];
        for (int t = 7; t >= 0; t--) {
            wv[t] = ba[t] * inv * powv;
            powv *= dec;
            s2 += wv[t];
        }
        #pragma unroll
        for (int t = 0; t < 8; t++) wsh[t] = wv[t];
        ssh = s2;
    }
    __syncthreads();
    float acc = 0.f;
    #pragma unroll
    for (int t = 0; t < 8; t++) acc += wsh[t] * nbv[t];
    __nv_bfloat16 hi, lo; bsplit(acc, hi, lo);
    wbh[(size_t)r * Cc + c] = hi;
    wbl[(size_t)r * Cc + c] = lo;
    if (c == 0) svec[r] = ssh;
}

// ---------------- launch ----------------
struct LaunchCtx {
    cudaStream_t s1, s2;
    cudaEvent_t eF, e1, e2;
    LaunchCtx() {
        int lo, hi;
        cudaDeviceGetStreamPriorityRange(&lo, &hi);
        cudaStreamCreateWithPriority(&s1, cudaStreamNonBlocking, hi);
        cudaStreamCreateWithPriority(&s2, cudaStreamNonBlocking, hi);
        cudaEventCreateWithFlags(&eF, cudaEventDisableTiming);
        cudaEventCreateWithFlags(&e1, cudaEventDisableTiming);
        cudaEventCreateWithFlags(&e2, cudaEventDisableTiming);
    }
};

extern "C" void kernel_launch(void* const* d_in, const int* in_sizes, int n_in,
                              void* d_out, int out_size) {
    (void)in_sizes; (void)n_in; (void)out_size;
    const float* q      = (const float*)d_in[0];
    const float* k      = (const float*)d_in[1];
    const float* v      = (const float*)d_in[2];
    const float* send   = (const float*)d_in[3];
    const float* recv   = (const float*)d_in[4];
    const float* ctrl   = (const float*)d_in[5];
    const float* h      = (const float*)d_in[6];
    const float* buffers= (const float*)d_in[7];
    const float* bond   = (const float*)d_in[8];
    const float* out_w  = (const float*)d_in[9];
    const float* out_b  = (const float*)d_in[10];
    const float* bq_w   = (const float*)d_in[11];
    const float* bq_b   = (const float*)d_in[12];
    const float* bk_w   = (const float*)d_in[13];
    const float* bk_b   = (const float*)d_in[14];
    const float* bv_w   = (const float*)d_in[15];
    const float* bv_b   = (const float*)d_in[16];
    const float* decay  = (const float*)d_in[17];

    float* out     = (float*)d_out;
    float* readout = out;                                   // [N,B,C]
    float* newbuf  = out + (size_t)Rr * Cc;                 // [N,B,T,C]
    float* attn    = newbuf + (size_t)Rr * Tt * Cc;         // [B,H,N,N]

    __nv_bfloat16 *p_msh, *p_msl, *p_wbh, *p_wbl, *p_hh, *p_hl;
    __nv_bfloat16 *p_owh, *p_owl, *p_bvh, *p_bvl, *p_w2h, *p_w2l;
    float *p_bqk, *p_s, *p_b2, *p_u;
    cudaGetSymbolAddress((void**)&p_msh, g_msh);
    cudaGetSymbolAddress((void**)&p_msl, g_msl);
    cudaGetSymbolAddress((void**)&p_wbh, g_wbh);
    cudaGetSymbolAddress((void**)&p_wbl, g_wbl);
    cudaGetSymbolAddress((void**)&p_hh,  g_hh);
    cudaGetSymbolAddress((void**)&p_hl,  g_hl);
    cudaGetSymbolAddress((void**)&p_owh, g_owt_h);
    cudaGetSymbolAddress((void**)&p_owl, g_owt_l);
    cudaGetSymbolAddress((void**)&p_bvh, g_bvt_h);
    cudaGetSymbolAddress((void**)&p_bvl, g_bvt_l);
    cudaGetSymbolAddress((void**)&p_w2h, g_w2t_h);
    cudaGetSymbolAddress((void**)&p_w2l, g_w2t_l);
    cudaGetSymbolAddress((void**)&p_bqk, g_bqk);
    cudaGetSymbolAddress((void**)&p_s,   g_s);
    cudaGetSymbolAddress((void**)&p_b2,  g_b2);
    cudaGetSymbolAddress((void**)&p_u,   g_u);

    cudaFuncSetAttribute(attn_kernel, cudaFuncAttributeMaxDynamicSharedMemorySize, ATTN_SMEM);
    cudaFuncSetAttribute(gemm_mma<EpiMsgs>, cudaFuncAttributeMaxDynamicSharedMemorySize, GEMM_SMEM);
    cudaFuncSetAttribute(gemm_mma<EpiBias>, cudaFuncAttributeMaxDynamicSharedMemorySize, GEMM_SMEM);
    cudaFuncSetAttribute(gemm_mma<EpiRead>, cudaFuncAttributeMaxDynamicSharedMemorySize, GEMM_SMEM);

    static LaunchCtx ctx;

    cudaEventRecord(ctx.eF, 0);
    cudaStreamWaitEvent(ctx.s1, ctx.eF, 0);
    cudaStreamWaitEvent(ctx.s2, ctx.eF, 0);

    // side streams first (priority; hidden under attn)
    wsplit_t2<<<dim3(8, 8, 2), 256, 0, ctx.s1>>>(out_w, p_owh, p_owl, bv_w, p_bvh, p_bvl);
    cudaEventRecord(ctx.e1, ctx.s1);

    // s2: bq/bk fold chain + bqk GEMM
    fold_small<<<385, 256, 0, ctx.s2>>>(bq_w, bq_b, bk_w, bk_b, p_b2, p_u);
    fold_w2<<<dim3(8, 16), 256, 0, ctx.s2>>>(bq_w, bk_w, p_w2h, p_w2l);
    split_h<<<1024, 256, 0, ctx.s2>>>(h, p_hh, p_hl);
    {   EpiBias e{p_bqk, p_b2};
        gemm_mma<EpiBias><<<dim3(128, 4), 256, GEMM_SMEM, ctx.s2>>>(p_hh, p_hl, p_w2h, p_w2l, 128, e); }
    cudaEventRecord(ctx.e2, ctx.s2);

    // main stream: attention (longest pole; backfills around side work)
    attn_kernel<<<Bb * Hh, 256, ATTN_SMEM>>>(q, k, v, send, ctrl, bond, p_msh, p_msl, attn);

    // join: msgs GEMM needs attn (main) + out_w split (s1)
    cudaStreamWaitEvent(0, ctx.e1, 0);
    {   EpiMsgs e{out_b, recv, newbuf};
        gemm_mma<EpiMsgs><<<dim3(128, 4), 256, GEMM_SMEM>>>(p_msh, p_msl, p_owh, p_owl, 256, e); }

    // temporal needs bqk (s2) + newbuf slot7 (main) + buffers
    cudaStreamWaitEvent(0, ctx.e2, 0);
    temporal_kernel<<<Rr, 256>>>(p_bqk, h, p_u, buffers, newbuf, decay, p_wbh, p_wbl, p_s);

    {   EpiRead e{readout, bv_b, p_s};
        gemm_mma<EpiRead><<<dim3(128, 4), 256, GEMM_SMEM>>>(p_wbh, p_wbl, p_bvh, p_bvl, 256, e); }
}

// round 17
// speedup vs baseline: 1.1120x; 1.0562x over previous
#include <cuda_runtime.h>
#include <cuda_bf16.h>
#include <cstdint>

#define Nn 64
#define Bb 256
#define Cc 256
#define Hh 4
#define HDd 64
#define Tt 8
#define Mm 128
#define Rr (Nn*Bb)   // 16384 rows

// ---------------- scratch (no allocations allowed) ----------------
__device__ __nv_bfloat16 g_msh[(size_t)Rr*Cc];   // msgs hi  [B*N, 256]
__device__ __nv_bfloat16 g_msl[(size_t)Rr*Cc];   // msgs lo
__device__ __nv_bfloat16 g_wbh[(size_t)Rr*Cc];   // wbuf hi  [N*B, 256]
__device__ __nv_bfloat16 g_wbl[(size_t)Rr*Cc];   // wbuf lo
__device__ __nv_bfloat16 g_hh [(size_t)Rr*Mm];   // h hi     [N*B, 128]
__device__ __nv_bfloat16 g_hl [(size_t)Rr*Mm];   // h lo
__device__ __nv_bfloat16 g_owt_h[(size_t)Cc*Cc]; // out_w^T hi  [n][k]
__device__ __nv_bfloat16 g_owt_l[(size_t)Cc*Cc];
__device__ __nv_bfloat16 g_bvt_h[(size_t)Cc*Cc]; // bv_w^T hi
__device__ __nv_bfloat16 g_bvt_l[(size_t)Cc*Cc];
__device__ __nv_bfloat16 g_w2t_h[(size_t)Cc*Mm]; // (bq_w@bk_w^T)^T hi [e][m]
__device__ __nv_bfloat16 g_w2t_l[(size_t)Cc*Mm];
__device__ float g_bqk [(size_t)Rr*Cc];          // [N*B, C]
__device__ float g_s   [(size_t)Rr];
__device__ float g_b2  [Cc];                     // bq_b @ bk_w^T
__device__ float g_u   [Mm + 1];                 // bq_w @ bk_b; [128]=bq_b.bk_b

// ================= helpers =================
__device__ __forceinline__ void bsplit(float x, __nv_bfloat16& hi, __nv_bfloat16& lo) {
    hi = __float2bfloat16(x);
    lo = __float2bfloat16(x - __bfloat162float(hi));
}
__device__ __forceinline__ uint32_t smem_u32(const void* p) {
    uint32_t a;
    asm("{ .reg .u64 t; cvta.to.shared.u64 t, %1; cvt.u32.u64 %0, t; }" : "=r"(a) : "l"(p));
    return a;
}
__device__ __forceinline__ void cp16(uint32_t d, const void* s) {
    asm volatile("cp.async.ca.shared.global [%0], [%1], 16;" :: "r"(d), "l"(s));
}
__device__ __forceinline__ void ldsm4(uint32_t* r, uint32_t a) {
    asm volatile("ldmatrix.sync.aligned.m8n8.x4.shared.b16 {%0,%1,%2,%3}, [%4];"
                 : "=r"(r[0]), "=r"(r[1]), "=r"(r[2]), "=r"(r[3]) : "r"(a));
}
__device__ __forceinline__ void mma16816(float* d, const uint32_t* a, const uint32_t* b) {
    asm volatile("mma.sync.aligned.m16n8k16.row.col.f32.bf16.bf16.f32 "
                 "{%0,%1,%2,%3}, {%4,%5,%6,%7}, {%8,%9}, {%0,%1,%2,%3};"
                 : "+f"(d[0]), "+f"(d[1]), "+f"(d[2]), "+f"(d[3])
                 : "r"(a[0]), "r"(a[1]), "r"(a[2]), "r"(a[3]), "r"(b[0]), "r"(b[1]));
}

// warp-level 16x32 tile of a 64x64x64 split-bf16 matmul (pitch 72 bf16 arrays)
__device__ __forceinline__ void warp_mm64(const __nv_bfloat16* Ah_, const __nv_bfloat16* Al_,
                                          const __nv_bfloat16* Bh_, const __nv_bfloat16* Bl_,
                                          int wband, int whalf, int lane, float acc[4][4]) {
    const int lg = lane >> 3, lr = lane & 7;
    #pragma unroll
    for (int kk = 0; kk < 4; kk++) {
        uint32_t Af[2][4];
        int arow = wband*16 + (lg & 1)*8 + lr;
        int akc  = kk*16 + (lg >> 1)*8;
        ldsm4(Af[0], smem_u32(Ah_ + arow*72 + akc));
        ldsm4(Af[1], smem_u32(Al_ + arow*72 + akc));
        uint32_t Bf[2][4][2];
        #pragma unroll
        for (int s = 0; s < 2; s++) {
            const __nv_bfloat16* Bp = s ? Bl_ : Bh_;
            #pragma unroll
            for (int nt2 = 0; nt2 < 2; nt2++) {
                int brow = whalf*32 + nt2*16 + (lg >> 1)*8 + lr;
                int bkc  = kk*16 + (lg & 1)*8;
                uint32_t r[4];
                ldsm4(r, smem_u32(Bp + brow*72 + bkc));
                Bf[s][nt2*2][0]   = r[0]; Bf[s][nt2*2][1]   = r[1];
                Bf[s][nt2*2+1][0] = r[2]; Bf[s][nt2*2+1][1] = r[3];
            }
        }
        #pragma unroll
        for (int nt = 0; nt < 4; nt++) {
            mma16816(acc[nt], Af[0], Bf[0][nt]);
            mma16816(acc[nt], Af[0], Bf[1][nt]);
            mma16816(acc[nt], Af[1], Bf[0][nt]);
        }
    }
}

// ============ weight folding ============
__global__ void fold_w2(const float* __restrict__ bq_w, const float* __restrict__ bk_w,
                        __nv_bfloat16* __restrict__ W2th, __nv_bfloat16* __restrict__ W2tl) {
    __shared__ float Aq[16*260];
    __shared__ float Bk[16*260];
    const int tid = threadIdx.x;
    const int m0 = blockIdx.x * 16;
    const int e0 = blockIdx.y * 16;
    #pragma unroll
    for (int i = 0; i < 4; i++) {
        int t = tid + i * 256;
        int row = t >> 6, c4 = (t & 63) * 4;
        *(float4*)&Aq[row*260 + c4] = *(const float4*)&bq_w[(size_t)(m0 + row) * 256 + c4];
        *(float4*)&Bk[row*260 + c4] = *(const float4*)&bk_w[(size_t)(e0 + row) * 256 + c4];
    }
    __syncthreads();
    const int m = tid >> 4, e = tid & 15;
    float acc = 0.f;
    #pragma unroll 4
    for (int c4 = 0; c4 < 256; c4 += 4) {
        float4 a = *(float4*)&Aq[m*260 + c4];
        float4 b = *(float4*)&Bk[e*260 + c4];
        acc += a.x*b.x + a.y*b.y + a.z*b.z + a.w*b.w;
    }
    __nv_bfloat16 hi, lo; bsplit(acc, hi, lo);
    size_t o = (size_t)(e0 + e) * Mm + (m0 + m);
    W2th[o] = hi; W2tl[o] = lo;
}

// parallel: one block per output element (0..255 -> b2, 256..383 -> u, 384 -> u[128])
__global__ void fold_small(const float* __restrict__ bq_w, const float* __restrict__ bq_b,
                           const float* __restrict__ bk_w, const float* __restrict__ bk_b,
                           float* __restrict__ b2, float* __restrict__ u) {
    const int o = blockIdx.x;
    const int c = threadIdx.x;     // 256
    float val;
    if (o < 256)      val = bq_b[c] * bk_w[(size_t)o * 256 + c];
    else if (o < 384) val = bq_w[(size_t)(o - 256) * 256 + c] * bk_b[c];
    else              val = bq_b[c] * bk_b[c];
    #pragma unroll
    for (int off = 16; off > 0; off >>= 1) val += __shfl_xor_sync(0xffffffffu, val, off);
    __shared__ float red[8];
    if ((c & 31) == 0) red[c >> 5] = val;
    __syncthreads();
    if (c == 0) {
        float s = 0.f;
        #pragma unroll
        for (int w = 0; w < 8; w++) s += red[w];
        if (o < 256) b2[o] = s;
        else if (o < 384) u[o - 256] = s;
        else u[128] = s;
    }
}

// split h [N*B,128] into bf16 hi/lo — grid-stride float4
__global__ void split_h(const float* __restrict__ h, __nv_bfloat16* __restrict__ hh,
                        __nv_bfloat16* __restrict__ hl) {
    const long total4 = (long)Rr * Mm / 4;
    for (long i4 = (long)blockIdx.x * blockDim.x + threadIdx.x; i4 < total4;
         i4 += (long)gridDim.x * blockDim.x) {
        float4 x = ((const float4*)h)[i4];
        __nv_bfloat16 h0,l0,h1,l1,h2,l2,h3,l3;
        bsplit(x.x,h0,l0); bsplit(x.y,h1,l1); bsplit(x.z,h2,l2); bsplit(x.w,h3,l3);
        __nv_bfloat162 a{h0,h1}, b2{h2,h3}, c{l0,l1}, d2{l2,l3};
        *(__nv_bfloat162*)&hh[i4*4]     = a;
        *(__nv_bfloat162*)&hh[i4*4 + 2] = b2;
        *(__nv_bfloat162*)&hl[i4*4]     = c;
        *(__nv_bfloat162*)&hl[i4*4 + 2] = d2;
    }
}

// transpose + split two 256x256 weights (z selects): out[n][k] = bf16split(W[k][n])
__global__ void wsplit_t2(const float* __restrict__ W0, __nv_bfloat16* __restrict__ th0,
                          __nv_bfloat16* __restrict__ tl0,
                          const float* __restrict__ W1, __nv_bfloat16* __restrict__ th1,
                          __nv_bfloat16* __restrict__ tl1) {
    const float* W = blockIdx.z ? W1 : W0;
    __nv_bfloat16* th = blockIdx.z ? th1 : th0;
    __nv_bfloat16* tl = blockIdx.z ? tl1 : tl0;
    __shared__ float tile[32][33];
    const int bx = blockIdx.x, by = blockIdx.y;
    const int tx = threadIdx.x & 31, ty0 = threadIdx.x >> 5;
    #pragma unroll
    for (int i = 0; i < 4; i++) {
        int kk = by*32 + ty0 + i*8;
        tile[ty0 + i*8][tx] = W[(size_t)kk * 256 + bx*32 + tx];
    }
    __syncthreads();
    #pragma unroll
    for (int i = 0; i < 4; i++) {
        int n = bx*32 + ty0 + i*8;
        int kk = by*32 + tx;
        __nv_bfloat16 hi, lo; bsplit(tile[tx][ty0 + i*8], hi, lo);
        th[(size_t)n*256 + kk] = hi; tl[(size_t)n*256 + kk] = lo;
    }
}

// ============ fused graph attention per (b,h) — hybrid: fp32 QK^T, HMMA A@V ============
__device__ __forceinline__ unsigned okey(float v) {
    unsigned u = __float_as_uint(v);
    return (u & 0x80000000u) ? ~u : (u | 0x80000000u);
}

#define ATTN_SMEM 54272

__global__ void attn_kernel(const float* __restrict__ q, const float* __restrict__ k,
                            const float* __restrict__ v, const float* __restrict__ sg,
                            const float* __restrict__ ctrl, const float* __restrict__ bond,
                            __nv_bfloat16* __restrict__ msh, __nv_bfloat16* __restrict__ msl,
                            float* __restrict__ attn_out) {
    extern __shared__ char smc[];
    float* QT = (float*)smc;                         // [64 d][68]
    float* KT = (float*)(smc + 17408);               // [64 d][68]
    __nv_bfloat16* Vh  = (__nv_bfloat16*)smc;        // [64 d][72]
    __nv_bfloat16* Vl  = (__nv_bfloat16*)(smc + 9216);
    __nv_bfloat16* Ash = (__nv_bfloat16*)(smc + 18432); // [64 n][72]
    __nv_bfloat16* Asl = (__nv_bfloat16*)(smc + 27648);
    float* Ls = (float*)(smc + 36864);               // [64 n][68]

    const int bid = blockIdx.x;
    const int b = bid >> 2;
    const int hh = bid & 3;
    const int tid = threadIdx.x, wid = tid >> 5, lane = tid & 31;

    // phase 1: load Q,K transposed fp32
    #pragma unroll
    for (int i = 0; i < 4; i++) {
        int t = tid + i * 256;
        int row = t >> 4;
        int col = (t & 15) * 4;
        size_t g = ((size_t)row * Bb + b) * Cc + hh * HDd + col;
        float4 qv = *(const float4*)&q[g];
        float4 kv = *(const float4*)&k[g];
        QT[(col+0)*68 + row] = qv.x; QT[(col+1)*68 + row] = qv.y;
        QT[(col+2)*68 + row] = qv.z; QT[(col+3)*68 + row] = qv.w;
        KT[(col+0)*68 + row] = kv.x; KT[(col+1)*68 + row] = kv.y;
        KT[(col+2)*68 + row] = kv.z; KT[(col+3)*68 + row] = kv.w;
    }
    __syncthreads();

    const int n0 = (tid >> 4) * 4;
    const int m0 = (tid & 15) * 4;

    // logits = Q @ K^T in fp32 (EXACT — selection depends on it)
    {
        float acc[4][4];
        #pragma unroll
        for (int i = 0; i < 4; i++)
            #pragma unroll
            for (int j = 0; j < 4; j++) acc[i][j] = 0.f;
        for (int d = 0; d < 64; d++) {
            float4 a  = *(float4*)&QT[d*68 + n0];
            float4 bv = *(float4*)&KT[d*68 + m0];
            float av[4] = {a.x, a.y, a.z, a.w};
            float bw[4] = {bv.x, bv.y, bv.z, bv.w};
            #pragma unroll
            for (int i = 0; i < 4; i++)
                #pragma unroll
                for (int j = 0; j < 4; j++) acc[i][j] += av[i] * bw[j];
        }
        float cb[4];
        #pragma unroll
        for (int j = 0; j < 4; j++)
            cb[j] = ctrl[((size_t)(m0 + j) * Bb + b) * Hh + hh];
        #pragma unroll
        for (int i = 0; i < 4; i++) {
            int n = n0 + i;
            float4 bd = *(const float4*)&bond[(size_t)n * Nn + m0];
            float vals[4];
            vals[0] = acc[i][0]*0.125f + bd.x + cb[0];
            vals[1] = acc[i][1]*0.125f + bd.y + cb[1];
            vals[2] = acc[i][2]*0.125f + bd.z + cb[2];
            vals[3] = acc[i][3]*0.125f + bd.w + cb[3];
            int dsel = n - m0;
            if (dsel >= 0 && dsel < 4) vals[dsel] = -1e30f;
            *(float4*)&Ls[n*68 + m0] = *(float4*)vals;
        }
    }
    __syncthreads();

    // phase 2a: load gated V as bf16 splits, VT layout [d][m]
    #pragma unroll
    for (int i = 0; i < 4; i++) {
        int t = tid + i * 256;
        int row = t >> 4;
        int col = (t & 15) * 4;
        size_t g = ((size_t)row * Bb + b) * Cc + hh * HDd + col;
        float4 vv = *(const float4*)&v[g];
        float4 gg = *(const float4*)&sg[g];
        vv.x *= gg.x; vv.y *= gg.y; vv.z *= gg.z; vv.w *= gg.w;
        float vs[4] = {vv.x, vv.y, vv.z, vv.w};
        #pragma unroll
        for (int j = 0; j < 4; j++) {
            __nv_bfloat16 hi, lo; bsplit(vs[j], hi, lo);
            Vh[(col + j)*72 + row] = hi;
            Vl[(col + j)*72 + row] = lo;
        }
    }

    // phase 2b: warp-parallel exact top-8 + softmax (two rows interleaved)
    const size_t ao_base = (((size_t)b * Hh + hh) * Nn) * Nn;
    for (int pp = 0; pp < 4; pp++) {
        const int rowA = wid * 8 + pp * 2;
        const int rowB = rowA + 1;
        float vA0 = Ls[rowA*68 + lane], vA1 = Ls[rowA*68 + lane + 32];
        float vB0 = Ls[rowB*68 + lane], vB1 = Ls[rowB*68 + lane + 32];
        unsigned kA0 = okey(vA0), kA1 = okey(vA1);
        unsigned kB0 = okey(vB0), kB1 = okey(vB1);
        bool sA0 = false, sA1 = false, sB0 = false, sB1 = false;
        float mxA = 0.f, mxB = 0.f;
        #pragma unroll
        for (int it = 0; it < 8; it++) {
            unsigned cA0 = sA0 ? 0u : kA0;
            unsigned cA1 = sA1 ? 0u : kA1;
            unsigned cB0 = sB0 ? 0u : kB0;
            unsigned cB1 = sB1 ? 0u : kB1;
            unsigned mA = cA0 > cA1 ? cA0 : cA1;
            unsigned mB = cB0 > cB1 ? cB0 : cB1;
            unsigned bestA = __reduce_max_sync(0xffffffffu, mA);
            unsigned bestB = __reduce_max_sync(0xffffffffu, mB);
            if (it == 0) {
                mxA = __uint_as_float((bestA & 0x80000000u) ? (bestA & 0x7fffffffu) : ~bestA);
                mxB = __uint_as_float((bestB & 0x80000000u) ? (bestB & 0x7fffffffu) : ~bestB);
            }
            unsigned bA0 = __ballot_sync(0xffffffffu, cA0 == bestA);
            unsigned bB0 = __ballot_sync(0xffffffffu, cB0 == bestB);
            if (bA0) {
                if (lane == __ffs(bA0) - 1) sA0 = true;
            } else {
                unsigned bA1 = __ballot_sync(0xffffffffu, cA1 == bestA);
                if (lane == __ffs(bA1) - 1) sA1 = true;
            }
            if (bB0) {
                if (lane == __ffs(bB0) - 1) sB0 = true;
            } else {
                unsigned bB1 = __ballot_sync(0xffffffffu, cB1 == bestB);
                if (lane == __ffs(bB1) - 1) sB1 = true;
            }
        }
        float eA0 = sA0 ? __expf(vA0 - mxA) : 0.f;
        float eA1 = sA1 ? __expf(vA1 - mxA) : 0.f;
        float eB0 = sB0 ? __expf(vB0 - mxB) : 0.f;
        float eB1 = sB1 ? __expf(vB1 - mxB) : 0.f;
        float sumA = eA0 + eA1, sumB = eB0 + eB1;
        #pragma unroll
        for (int o = 16; o > 0; o >>= 1) {
            sumA += __shfl_xor_sync(0xffffffffu, sumA, o);
            sumB += __shfl_xor_sync(0xffffffffu, sumB, o);
        }
        float invA = 1.f / sumA, invB = 1.f / sumB;
        eA0 *= invA; eA1 *= invA; eB0 *= invB; eB1 *= invB;
        attn_out[ao_base + (size_t)rowA * Nn + lane]      = eA0;
        attn_out[ao_base + (size_t)rowA * Nn + lane + 32] = eA1;
        attn_out[ao_base + (size_t)rowB * Nn + lane]      = eB0;
        attn_out[ao_base + (size_t)rowB * Nn + lane + 32] = eB1;
        __nv_bfloat16 hi, lo;
        bsplit(eA0, hi, lo); Ash[rowA*72 + lane] = hi;      Asl[rowA*72 + lane] = lo;
        bsplit(eA1, hi, lo); Ash[rowA*72 + lane + 32] = hi; Asl[rowA*72 + lane + 32] = lo;
        bsplit(eB0, hi, lo); Ash[rowB*72 + lane] = hi;      Asl[rowB*72 + lane] = lo;
        bsplit(eB1, hi, lo); Ash[rowB*72 + lane + 32] = hi; Asl[rowB*72 + lane + 32] = lo;
    }
    __syncthreads();

    // phase 2c: msgs = attn @ Vg via split-bf16 HMMA
    {
        const int wband = wid >> 1;
        const int whalf = wid & 1;
        const int g2 = lane >> 2, tg = lane & 3;
        float acc[4][4];
        #pragma unroll
        for (int nt = 0; nt < 4; nt++)
            #pragma unroll
            for (int j = 0; j < 4; j++) acc[nt][j] = 0.f;
        warp_mm64(Ash, Asl, Vh, Vl, wband, whalf, lane, acc);
        #pragma unroll
        for (int nt = 0; nt < 4; nt++)
            #pragma unroll
            for (int dd = 0; dd < 2; dd++) {
                int n = wband*16 + g2 + dd*8;
                int d0c = whalf*32 + nt*8 + tg*2;
                size_t o = ((size_t)b * Nn + n) * Cc + hh * HDd + d0c;
                __nv_bfloat16 h0,l0,h1,l1;
                bsplit(acc[nt][dd*2+0], h0, l0);
                bsplit(acc[nt][dd*2+1], h1, l1);
                __nv_bfloat162 ph{h0,h1}, pl{l0,l1};
                *(__nv_bfloat162*)&msh[o] = ph;
                *(__nv_bfloat162*)&msl[o] = pl;
            }
    }
}

// ============ split-bf16 HMMA GEMM: [16384 x K] @ [K x 256] ============
// epilogues take contiguous column pairs (c, c+1) — float2 vectorized
struct EpiMsgs {
    const float* out_b; const float* recv; float* nb;
    __device__ __forceinline__ void store2(int r, int c, float a0, float a1) const {
        int n = r & 63, b = r >> 6;
        size_t rb = (size_t)n * Bb + b;
        float2 rv = *(const float2*)&recv[rb * Cc + c];
        float2 bb = *(const float2*)&out_b[c];
        float2 ov{(a0 + bb.x) * rv.x, (a1 + bb.y) * rv.y};
        *(float2*)&nb[(rb * Tt + (Tt - 1)) * Cc + c] = ov;
    }
};
struct EpiBias {
    float* out; const float* bias;
    __device__ __forceinline__ void store2(int r, int c, float a0, float a1) const {
        float2 bb = *(const float2*)&bias[c];
        float2 ov{a0 + bb.x, a1 + bb.y};
        *(float2*)&out[(size_t)r * Cc + c] = ov;
    }
};
struct EpiRead {
    float* out; const float* bias; const float* s;
    __device__ __forceinline__ void store2(int r, int c, float a0, float a1) const {
        float2 bb = *(const float2*)&bias[c];
        float sv = s[r];
        float2 ov{a0 + sv * bb.x, a1 + sv * bb.y};
        *(float2*)&out[(size_t)r * Cc + c] = ov;
    }
};

#define GEMM_SMEM (40960 + 20480)

template<typename Epi>
__global__ void __launch_bounds__(256, 2)
gemm_mma(const __nv_bfloat16* __restrict__ Ah, const __nv_bfloat16* __restrict__ Al,
         const __nv_bfloat16* __restrict__ Bth, const __nv_bfloat16* __restrict__ Btl,
         int K, Epi epi) {
    extern __shared__ char smem[];
    const uint32_t sbA = smem_u32(smem);
    const uint32_t sbB = sbA + 40960;
    const int tid = threadIdx.x, wid = tid >> 5, lane = tid & 31;
    const int r0 = blockIdx.x * 128, c0 = blockIdx.y * 64;
    const int wm = (wid & 3) * 32, wn = (wid >> 2) * 32;
    const int NS = K >> 5;

    float acc[2][4][4];
    #pragma unroll
    for (int mt = 0; mt < 2; mt++)
        #pragma unroll
        for (int nt = 0; nt < 4; nt++)
            #pragma unroll
            for (int j = 0; j < 4; j++) acc[mt][nt][j] = 0.f;

    auto loadChunk = [&](int stage, int buf) {
        const char* srcAh = (const char*)(Ah + (size_t)r0 * K + stage * 32);
        const char* srcAl = (const char*)(Al + (size_t)r0 * K + stage * 32);
        #pragma unroll
        for (int i = 0; i < 4; i++) {
            int ch = tid + i * 256;
            int s = ch >> 9;
            int rem = ch & 511;
            int row = rem >> 2, seg = rem & 3;
            uint32_t dst = sbA + (uint32_t)(((buf*2 + s)*128 + row) * 80 + seg * 16);
            const char* src = (s ? srcAl : srcAh) + (size_t)row * (K * 2) + seg * 16;
            cp16(dst, src);
        }
        const char* srcBh = (const char*)(Bth + (size_t)c0 * K + stage * 32);
        const char* srcBl = (const char*)(Btl + (size_t)c0 * K + stage * 32);
        #pragma unroll
        for (int i = 0; i < 2; i++) {
            int ch = tid + i * 256;
            int s = ch >> 8;
            int rem = ch & 255;
            int row = rem >> 2, seg = rem & 3;
            uint32_t dst = sbB + (uint32_t)(((buf*2 + s)*64 + row) * 80 + seg * 16);
            const char* src = (s ? srcBl : srcBh) + (size_t)row * (K * 2) + seg * 16;
            cp16(dst, src);
        }
        asm volatile("cp.async.commit_group;");
    };

    loadChunk(0, 0);

    const int lg = lane >> 3, lr = lane & 7;

    for (int i = 0; i < NS; i++) {
        if (i + 1 < NS) {
            loadChunk(i + 1, (i + 1) & 1);
            asm volatile("cp.async.wait_group 1;");
        } else {
            asm volatile("cp.async.wait_group 0;");
        }
        __syncthreads();
        int buf = i & 1;
        #pragma unroll
        for (int kk = 0; kk < 2; kk++) {
            uint32_t Af[2][2][4];
            uint32_t Bf[2][4][2];
            #pragma unroll
            for (int s = 0; s < 2; s++)
                #pragma unroll
                for (int mt = 0; mt < 2; mt++) {
                    int row = wm + mt*16 + (lg & 1)*8 + lr;
                    int kc  = kk*16 + (lg >> 1)*8;
                    ldsm4(Af[s][mt], sbA + (uint32_t)(((buf*2 + s)*128 + row)*80 + kc*2));
                }
            #pragma unroll
            for (int s = 0; s < 2; s++)
                #pragma unroll
                for (int nt2 = 0; nt2 < 2; nt2++) {
                    int row = wn + nt2*16 + (lg >> 1)*8 + lr;
                    int kc  = kk*16 + (lg & 1)*8;
                    uint32_t r[4];
                    ldsm4(r, sbB + (uint32_t)(((buf*2 + s)*64 + row)*80 + kc*2));
                    Bf[s][nt2*2][0]   = r[0]; Bf[s][nt2*2][1]   = r[1];
                    Bf[s][nt2*2+1][0] = r[2]; Bf[s][nt2*2+1][1] = r[3];
                }
            #pragma unroll
            for (int mt = 0; mt < 2; mt++)
                #pragma unroll
                for (int nt = 0; nt < 4; nt++) {
                    mma16816(acc[mt][nt], Af[0][mt], Bf[0][nt]);
                    mma16816(acc[mt][nt], Af[0][mt], Bf[1][nt]);
                    mma16816(acc[mt][nt], Af[1][mt], Bf[0][nt]);
                }
        }
        __syncthreads();
    }

    const int g = lane >> 2, tg = lane & 3;
    #pragma unroll
    for (int mt = 0; mt < 2; mt++)
        #pragma unroll
        for (int nt = 0; nt < 4; nt++) {
            int row = r0 + wm + mt*16 + g;
            int col = c0 + wn + nt*8 + tg*2;
            epi.store2(row,     col, acc[mt][nt][0], acc[mt][nt][1]);
            epi.store2(row + 8, col, acc[mt][nt][2], acc[mt][nt][3]);
        }
}

// ---------------- temporal (float4): 4 rows/block, fused shift + softmax + weighted sum ----------------
__global__ void temporal_kernel(const float* __restrict__ bqk,
                                const float* __restrict__ h,
                                const float* __restrict__ u,
                                const float* __restrict__ buffers,
                                float* __restrict__ newbuf,
                                const float* __restrict__ decay_logit,
                                __nv_bfloat16* __restrict__ wbh,
                                __nv_bfloat16* __restrict__ wbl,
                                float* __restrict__ svec) {
    const int tid = threadIdx.x;
    const int row = tid >> 6;                  // 0..3 within block
    const int g = tid & 63;                    // column group
    const int r = blockIdx.x * 4 + row;        // global row (n*B + b)
    const int c = g * 4;
    const float* ob = buffers + (size_t)r * (Tt * Cc);
    float* nb = newbuf + (size_t)r * (Tt * Cc);

    float4 qk = *(const float4*)&bqk[(size_t)r * Cc + c];
    float4 nbv[8];
    #pragma unroll
    for (int t = 0; t < 7; t++) nbv[t] = *(const float4*)&ob[(t + 1) * Cc + c];
    nbv[7] = *(const float4*)&nb[7 * Cc + c];

    float p[9];
    #pragma unroll
    for (int t = 0; t < 8; t++)
        p[t] = qk.x*nbv[t].x + qk.y*nbv[t].y + qk.z*nbv[t].z + qk.w*nbv[t].w;
    p[8] = 0.f;
    if (g < 32) {
        float4 hv = *(const float4*)&h[(size_t)r * Mm + g * 4];
        float4 uv = *(const float4*)&u[g * 4];
        p[8] = hv.x*uv.x + hv.y*uv.y + hv.z*uv.z + hv.w*uv.w;
    }

    // fused shift: write slots 0..6 (float4)
    #pragma unroll
    for (int t = 0; t < 7; t++) *(float4*)&nb[t * Cc + c] = nbv[t];

    #pragma unroll
    for (int t = 0; t < 9; t++)
        #pragma unroll
        for (int o = 16; o > 0; o >>= 1)
            p[t] += __shfl_xor_sync(0xffffffffu, p[t], o);

    __shared__ float red[8][9];   // per warp
    __shared__ float wsh[4][8];
    __shared__ float ssh[4];
    const int warp = tid >> 5, lane = tid & 31;
    if (lane == 0) {
        #pragma unroll
        for (int t = 0; t < 9; t++) red[warp][t] = p[t];
    }
    __syncthreads();
    if (g == 0) {                 // one leader per row (4 leaders)
        float bqb = u[128] + red[2*row][8] + red[2*row + 1][8];
        float ba[8]; float mx = -3e38f;
        #pragma unroll
        for (int t = 0; t < 8; t++) {
            ba[t] = (red[2*row][t] + red[2*row + 1][t] + bqb) * 0.0625f;
            mx = fmaxf(mx, ba[t]);
        }
        float sum = 0.f;
        #pragma unroll
        for (int t = 0; t < 8; t++) { ba[t] = __expf(ba[t] - mx); sum += ba[t]; }
        float inv = 1.f / sum;
        float dec = 1.f / (1.f + __expf(-decay_logit[0]));
        float powv = dec, s2 = 0.f;
        float wv[8];
        for (int t = 7; t >= 0; t--) {
            wv[t] = ba[t] * inv * powv;
            powv *= dec;
            s2 += wv[t];
        }
        #pragma unroll
        for (int t = 0; t < 8; t++) wsh[row][t] = wv[t];
        ssh[row] = s2;
    }
    __syncthreads();
    float4 acc{0.f, 0.f, 0.f, 0.f};
    #pragma unroll
    for (int t = 0; t < 8; t++) {
        float w = wsh[row][t];
        acc.x += w * nbv[t].x; acc.y += w * nbv[t].y;
        acc.z += w * nbv[t].z; acc.w += w * nbv[t].w;
    }
    __nv_bfloat16 h0,l0,h1,l1,h2,l2,h3,l3;
    bsplit(acc.x,h0,l0); bsplit(acc.y,h1,l1); bsplit(acc.z,h2,l2); bsplit(acc.w,h3,l3);
    __nv_bfloat162 ph0{h0,h1}, ph1{h2,h3}, pl0{l0,l1}, pl1{l2,l3};
    uint2 hv{*(uint32_t*)&ph0, *(uint32_t*)&ph1};
    uint2 lv{*(uint32_t*)&pl0, *(uint32_t*)&pl1};
    *(uint2*)&wbh[(size_t)r * Cc + c] = hv;
    *(uint2*)&wbl[(size_t)r * Cc + c] = lv;
    if (g == 0) svec[r] = ssh[row];
}

// ---------------- launch ----------------
struct LaunchCtx {
    cudaStream_t s1, s2;
    cudaEvent_t eF, e1, e2;
    LaunchCtx() {
        int lo, hi;
        cudaDeviceGetStreamPriorityRange(&lo, &hi);
        cudaStreamCreateWithPriority(&s1, cudaStreamNonBlocking, hi);
        cudaStreamCreateWithPriority(&s2, cudaStreamNonBlocking, hi);
        cudaEventCreateWithFlags(&eF, cudaEventDisableTiming);
        cudaEventCreateWithFlags(&e1, cudaEventDisableTiming);
        cudaEventCreateWithFlags(&e2, cudaEventDisableTiming);
    }
};

extern "C" void kernel_launch(void* const* d_in, const int* in_sizes, int n_in,
                              void* d_out, int out_size) {
    (void)in_sizes; (void)n_in; (void)out_size;
    const float* q      = (const float*)d_in[0];
    const float* k      = (const float*)d_in[1];
    const float* v      = (const float*)d_in[2];
    const float* send   = (const float*)d_in[3];
    const float* recv   = (const float*)d_in[4];
    const float* ctrl   = (const float*)d_in[5];
    const float* h      = (const float*)d_in[6];
    const float* buffers= (const float*)d_in[7];
    const float* bond   = (const float*)d_in[8];
    const float* out_w  = (const float*)d_in[9];
    const float* out_b  = (const float*)d_in[10];
    const float* bq_w   = (const float*)d_in[11];
    const float* bq_b   = (const float*)d_in[12];
    const float* bk_w   = (const float*)d_in[13];
    const float* bk_b   = (const float*)d_in[14];
    const float* bv_w   = (const float*)d_in[15];
    const float* bv_b   = (const float*)d_in[16];
    const float* decay  = (const float*)d_in[17];

    float* out     = (float*)d_out;
    float* readout = out;                                   // [N,B,C]
    float* newbuf  = out + (size_t)Rr * Cc;                 // [N,B,T,C]
    float* attn    = newbuf + (size_t)Rr * Tt * Cc;         // [B,H,N,N]

    __nv_bfloat16 *p_msh, *p_msl, *p_wbh, *p_wbl, *p_hh, *p_hl;
    __nv_bfloat16 *p_owh, *p_owl, *p_bvh, *p_bvl, *p_w2h, *p_w2l;
    float *p_bqk, *p_s, *p_b2, *p_u;
    cudaGetSymbolAddress((void**)&p_msh, g_msh);
    cudaGetSymbolAddress((void**)&p_msl, g_msl);
    cudaGetSymbolAddress((void**)&p_wbh, g_wbh);
    cudaGetSymbolAddress((void**)&p_wbl, g_wbl);
    cudaGetSymbolAddress((void**)&p_hh,  g_hh);
    cudaGetSymbolAddress((void**)&p_hl,  g_hl);
    cudaGetSymbolAddress((void**)&p_owh, g_owt_h);
    cudaGetSymbolAddress((void**)&p_owl, g_owt_l);
    cudaGetSymbolAddress((void**)&p_bvh, g_bvt_h);
    cudaGetSymbolAddress((void**)&p_bvl, g_bvt_l);
    cudaGetSymbolAddress((void**)&p_w2h, g_w2t_h);
    cudaGetSymbolAddress((void**)&p_w2l, g_w2t_l);
    cudaGetSymbolAddress((void**)&p_bqk, g_bqk);
    cudaGetSymbolAddress((void**)&p_s,   g_s);
    cudaGetSymbolAddress((void**)&p_b2,  g_b2);
    cudaGetSymbolAddress((void**)&p_u,   g_u);

    cudaFuncSetAttribute(attn_kernel, cudaFuncAttributeMaxDynamicSharedMemorySize, ATTN_SMEM);
    cudaFuncSetAttribute(gemm_mma<EpiMsgs>, cudaFuncAttributeMaxDynamicSharedMemorySize, GEMM_SMEM);
    cudaFuncSetAttribute(gemm_mma<EpiBias>, cudaFuncAttributeMaxDynamicSharedMemorySize, GEMM_SMEM);
    cudaFuncSetAttribute(gemm_mma<EpiRead>, cudaFuncAttributeMaxDynamicSharedMemorySize, GEMM_SMEM);

    static LaunchCtx ctx;

    cudaEventRecord(ctx.eF, 0);
    cudaStreamWaitEvent(ctx.s1, ctx.eF, 0);
    cudaStreamWaitEvent(ctx.s2, ctx.eF, 0);

    // side streams first (priority; hidden under attn)
    wsplit_t2<<<dim3(8, 8, 2), 256, 0, ctx.s1>>>(out_w, p_owh, p_owl, bv_w, p_bvh, p_bvl);
    cudaEventRecord(ctx.e1, ctx.s1);

    // s2: bq/bk fold chain + bqk GEMM
    fold_small<<<385, 256, 0, ctx.s2>>>(bq_w, bq_b, bk_w, bk_b, p_b2, p_u);
    fold_w2<<<dim3(8, 16), 256, 0, ctx.s2>>>(bq_w, bk_w, p_w2h, p_w2l);
    split_h<<<1024, 256, 0, ctx.s2>>>(h, p_hh, p_hl);
    {   EpiBias e{p_bqk, p_b2};
        gemm_mma<EpiBias><<<dim3(128, 4), 256, GEMM_SMEM, ctx.s2>>>(p_hh, p_hl, p_w2h, p_w2l, 128, e); }
    cudaEventRecord(ctx.e2, ctx.s2);

    // main stream: attention (longest pole; backfills around side work)
    attn_kernel<<<Bb * Hh, 256, ATTN_SMEM>>>(q, k, v, send, ctrl, bond, p_msh, p_msl, attn);

    // join: msgs GEMM needs attn (main) + out_w split (s1)
    cudaStreamWaitEvent(0, ctx.e1, 0);
    {   EpiMsgs e{out_b, recv, newbuf};
        gemm_mma<EpiMsgs><<<dim3(128, 4), 256, GEMM_SMEM>>>(p_msh, p_msl, p_owh, p_owl, 256, e); }

    // temporal needs bqk (s2) + newbuf slot7 (main) + buffers
    cudaStreamWaitEvent(0, ctx.e2, 0);
    temporal_kernel<<<Rr / 4, 256>>>(p_bqk, h, p_u, buffers, newbuf, decay, p_wbh, p_wbl, p_s);

    {   EpiRead e{readout, bv_b, p_s};
        gemm_mma<EpiRead><<<dim3(128, 4), 256, GEMM_SMEM>>>(p_wbh, p_wbl, p_bvh, p_bvl, 256, e); }
}